// round 12
// baseline (speedup 1.0000x reference)
#include <cuda_runtime.h>

// Problem constants
#define Tn 512
#define Bn 8
#define Hn 256
#define Vn 32000
#define Ln 3
#define Mn (Tn*Bn)   // 4096
#define BH (Bn*Hn)   // 2048

// Scratch (device globals; allocation forbidden in kernel_launch)
__device__ float g_cur[Mn*Hn];
__device__ float g_spk[Mn*Hn];
__device__ float g_h  [Mn*Hn];
__device__ int   g_fcur[Mn];
__device__ int   g_fs  [Mn];
__device__ int   g_fh  [Mn];

#define MT 64
#define NT 64
#define KT 16
#define SLAB 32   // k-slab for gemm_embed

// ---------------------------------------------------------------------------
// tf32 mma.sync (m16n8k8, row.col, fp32 accum). Raw fp32 bits as tf32 (RZ).
// Precision: spike threshold sits ~11 sigma above |mem| on these scales, so
// tf32 rounding of cur cannot flip any spike (empirically rel_err=0).
// ---------------------------------------------------------------------------
__device__ __forceinline__ void mma_tf32(float* d, const unsigned* a,
                                         const unsigned* b) {
    asm volatile(
        "mma.sync.aligned.m16n8k8.row.col.f32.tf32.tf32.f32 "
        "{%0,%1,%2,%3}, {%4,%5,%6,%7}, {%8,%9}, {%0,%1,%2,%3};"
        : "+f"(d[0]), "+f"(d[1]), "+f"(d[2]), "+f"(d[3])
        : "r"(a[0]), "r"(a[1]), "r"(a[2]), "r"(a[3]),
          "r"(b[0]), "r"(b[1]));
}

// ---------------------------------------------------------------------------
// Layer-0 q-GEMM with fused embedding — tf32, double-buffered (R10 winner).
// Also: fcur=1, fs=0.
// ---------------------------------------------------------------------------
__global__ void __launch_bounds__(256)
gemm_embed_kernel(const int* __restrict__ tokens,
                  const float* __restrict__ tok_emb,
                  const float* __restrict__ pos_emb,
                  const float* __restrict__ W,
                  const float* __restrict__ bias,
                  float* __restrict__ C,
                  int* __restrict__ fcur,
                  int* __restrict__ fs_zero) {
    __shared__ __align__(16) float As[2][MT][SLAB + 4];   // stride 36
    __shared__ __align__(16) float Ws[2][SLAB][NT + 8];   // stride 72
    __shared__ int stok[MT];

    const int bm = blockIdx.y * MT;
    const int bn = blockIdx.x * NT;
    const int tid = threadIdx.x;
    const int wid = tid >> 5;
    const int lane = tid & 31;

    if (tid < MT) stok[tid] = tokens[bm + tid];
    if (blockIdx.x == 0 && tid < MT) {
        fcur[bm + tid] = 1;
        fs_zero[bm + tid] = 0;
    }
    __syncthreads();

    const int af0 = tid,        ar0s = af0 >> 3, ak0s = (af0 & 7) * 4;
    const int af1 = tid + 256,  ar1s = af1 >> 3, ak1s = (af1 & 7) * 4;
    const int wf0 = tid,        wk0s = wf0 >> 4, wn0s = (wf0 & 15) * 4;
    const int wf1 = tid + 256,  wk1s = wf1 >> 4, wn1s = (wf1 & 15) * 4;
    const long long atok0 = (long long)stok[ar0s] * Hn;
    const long long atok1 = (long long)stok[ar1s] * Hn;
    const int apos0 = ((bm + ar0s) >> 3) * Hn;
    const int apos1 = ((bm + ar1s) >> 3) * Hn;

    float4 ra0, ra1, rw0, rw1;
    {
        float4 e0 = *reinterpret_cast<const float4*>(&tok_emb[atok0 + ak0s]);
        float4 p0 = *reinterpret_cast<const float4*>(&pos_emb[apos0 + ak0s]);
        ra0 = make_float4(e0.x+p0.x, e0.y+p0.y, e0.z+p0.z, e0.w+p0.w);
        float4 e1 = *reinterpret_cast<const float4*>(&tok_emb[atok1 + ak1s]);
        float4 p1 = *reinterpret_cast<const float4*>(&pos_emb[apos1 + ak1s]);
        ra1 = make_float4(e1.x+p1.x, e1.y+p1.y, e1.z+p1.z, e1.w+p1.w);
        rw0 = *reinterpret_cast<const float4*>(&W[(long long)wk0s*Hn + bn + wn0s]);
        rw1 = *reinterpret_cast<const float4*>(&W[(long long)wk1s*Hn + bn + wn1s]);
    }
    *reinterpret_cast<float4*>(&As[0][ar0s][ak0s]) = ra0;
    *reinterpret_cast<float4*>(&As[0][ar1s][ak1s]) = ra1;
    *reinterpret_cast<float4*>(&Ws[0][wk0s][wn0s]) = rw0;
    *reinterpret_cast<float4*>(&Ws[0][wk1s][wn1s]) = rw1;
    __syncthreads();

    float d[4][4];
    #pragma unroll
    for (int nf = 0; nf < 4; nf++)
        #pragma unroll
        for (int i = 0; i < 4; i++) d[nf][i] = 0.0f;

    const int strip = (wid >> 1) * 16;
    const int nh    = (wid & 1) * 32;
    const int ar0 = strip + (lane >> 2);
    const int ac0 = lane & 3;
    const int bk0 = lane & 3;
    const int bn0 = lane >> 2;

    const int NSLAB = Hn / SLAB;
    for (int s = 0; s < NSLAB; s++) {
        const int cb = s & 1;
        if (s + 1 < NSLAB) {
            int k0 = (s + 1) * SLAB;
            float4 e0 = *reinterpret_cast<const float4*>(&tok_emb[atok0 + k0 + ak0s]);
            float4 p0 = *reinterpret_cast<const float4*>(&pos_emb[apos0 + k0 + ak0s]);
            ra0 = make_float4(e0.x+p0.x, e0.y+p0.y, e0.z+p0.z, e0.w+p0.w);
            float4 e1 = *reinterpret_cast<const float4*>(&tok_emb[atok1 + k0 + ak1s]);
            float4 p1 = *reinterpret_cast<const float4*>(&pos_emb[apos1 + k0 + ak1s]);
            ra1 = make_float4(e1.x+p1.x, e1.y+p1.y, e1.z+p1.z, e1.w+p1.w);
            rw0 = *reinterpret_cast<const float4*>(&W[(long long)(k0 + wk0s)*Hn + bn + wn0s]);
            rw1 = *reinterpret_cast<const float4*>(&W[(long long)(k0 + wk1s)*Hn + bn + wn1s]);
        }

        #pragma unroll
        for (int kb = 0; kb < SLAB; kb += 8) {
            unsigned a[4];
            a[0] = __float_as_uint(As[cb][ar0    ][kb + ac0    ]);
            a[1] = __float_as_uint(As[cb][ar0 + 8][kb + ac0    ]);
            a[2] = __float_as_uint(As[cb][ar0    ][kb + ac0 + 4]);
            a[3] = __float_as_uint(As[cb][ar0 + 8][kb + ac0 + 4]);
            #pragma unroll
            for (int nf = 0; nf < 4; nf++) {
                unsigned b[2];
                b[0] = __float_as_uint(Ws[cb][kb + bk0    ][nh + nf*8 + bn0]);
                b[1] = __float_as_uint(Ws[cb][kb + bk0 + 4][nh + nf*8 + bn0]);
                mma_tf32(d[nf], a, b);
            }
        }

        if (s + 1 < NSLAB) {
            const int nb = (s + 1) & 1;
            *reinterpret_cast<float4*>(&As[nb][ar0s][ak0s]) = ra0;
            *reinterpret_cast<float4*>(&As[nb][ar1s][ak1s]) = ra1;
            *reinterpret_cast<float4*>(&Ws[nb][wk0s][wn0s]) = rw0;
            *reinterpret_cast<float4*>(&Ws[nb][wk1s][wn1s]) = rw1;
            __syncthreads();
        }
    }

    const int orow = strip + (lane >> 2);
    const int oc = (lane & 3) * 2;
    #pragma unroll
    for (int nf = 0; nf < 4; nf++) {
        int c = bn + nh + nf*8 + oc;
        float b0 = bias[c], b1 = bias[c + 1];
        float2 o0 = make_float2(d[nf][0] + b0, d[nf][1] + b1);
        float2 o1 = make_float2(d[nf][2] + b0, d[nf][3] + b1);
        *reinterpret_cast<float2*>(&C[(long long)(bm + orow)*Hn + c])     = o0;
        *reinterpret_cast<float2*>(&C[(long long)(bm + orow + 8)*Hn + c]) = o1;
    }
}

// ---------------------------------------------------------------------------
// FUSED fc_l + q_{l+1} (R11 winner): one block owns a 64-row m-strip.
// ---------------------------------------------------------------------------
__global__ void __launch_bounds__(256)
fused_fc_q_kernel(const float* __restrict__ spk,
                  const float* __restrict__ Wfc,
                  const float* __restrict__ bfc,
                  const float* __restrict__ Wq,
                  const float* __restrict__ bq,
                  float* __restrict__ h,
                  float* __restrict__ cur,
                  int* __restrict__ fs,
                  int* __restrict__ fcur)
{
    __shared__ __align__(16) float As[MT][KT + 1];
    __shared__ __align__(16) float Ws[KT][NT + 4];
    __shared__ int sflag[MT];

    const int bm = blockIdx.x * MT;
    const int tid = threadIdx.x;

    if (tid < MT) sflag[tid] = fs[bm + tid];
    int bfcAny = __syncthreads_or(bfc[tid] != 0.0f);
    int bqAny  = __syncthreads_or(bq[tid]  != 0.0f);
    int anyflag = __syncthreads_or(tid < MT ? sflag[tid] : 0);
    if (tid < MT) fs[bm + tid] = 0;

    if (!anyflag && !bfcAny) {
        if (tid < MT) fcur[bm + tid] = bqAny;
        if (bqAny) {
            int c4 = (tid & 63) * 4;
            int r0 = tid >> 6;
            float4 bv = *reinterpret_cast<const float4*>(&bq[c4]);
            #pragma unroll
            for (int r = r0; r < MT; r += 4)
                *reinterpret_cast<float4*>(&cur[(long long)(bm + r)*Hn + c4]) = bv;
        }
        return;
    }

    if (tid < MT) fcur[bm + tid] = 1;

    const int ty = tid >> 3;
    const int tx = tid & 7;
    const int arow = tid >> 2, akq = (tid & 3) * 4;
    const int wkk = tid >> 4, wnq = (tid & 15) * 4;

    // phase 1: fc (masked spk) -> h strip
    for (int nt = 0; nt < 4; nt++) {
        const int bn = nt * NT;
        float acc[2][8];
        #pragma unroll
        for (int i = 0; i < 2; i++)
            #pragma unroll
            for (int j = 0; j < 8; j++) acc[i][j] = 0.0f;

        for (int k0 = 0; k0 < Hn; k0 += KT) {
            float4 a4 = *reinterpret_cast<const float4*>(
                &spk[(long long)(bm + arow)*Hn + k0 + akq]);
            if (!sflag[arow]) { a4.x = a4.y = a4.z = a4.w = 0.0f; }
            As[arow][akq + 0] = a4.x; As[arow][akq + 1] = a4.y;
            As[arow][akq + 2] = a4.z; As[arow][akq + 3] = a4.w;
            *reinterpret_cast<float4*>(&Ws[wkk][wnq]) =
                *reinterpret_cast<const float4*>(
                    &Wfc[(long long)(k0 + wkk)*Hn + bn + wnq]);
            __syncthreads();

            #pragma unroll
            for (int k = 0; k < KT; k++) {
                float a0 = As[ty*2    ][k];
                float a1 = As[ty*2 + 1][k];
                float4 w0 = *reinterpret_cast<const float4*>(&Ws[k][tx*8]);
                float4 w1 = *reinterpret_cast<const float4*>(&Ws[k][tx*8 + 4]);
                float wv[8] = {w0.x, w0.y, w0.z, w0.w, w1.x, w1.y, w1.z, w1.w};
                #pragma unroll
                for (int j = 0; j < 8; j++) {
                    acc[0][j] = fmaf(a0, wv[j], acc[0][j]);
                    acc[1][j] = fmaf(a1, wv[j], acc[1][j]);
                }
            }
            __syncthreads();
        }

        #pragma unroll
        for (int i = 0; i < 2; i++) {
            int row = bm + ty*2 + i;
            float4 o0, o1;
            o0.x = fmaxf(acc[i][0] + bfc[bn + tx*8 + 0], 0.0f);
            o0.y = fmaxf(acc[i][1] + bfc[bn + tx*8 + 1], 0.0f);
            o0.z = fmaxf(acc[i][2] + bfc[bn + tx*8 + 2], 0.0f);
            o0.w = fmaxf(acc[i][3] + bfc[bn + tx*8 + 3], 0.0f);
            o1.x = fmaxf(acc[i][4] + bfc[bn + tx*8 + 4], 0.0f);
            o1.y = fmaxf(acc[i][5] + bfc[bn + tx*8 + 5], 0.0f);
            o1.z = fmaxf(acc[i][6] + bfc[bn + tx*8 + 6], 0.0f);
            o1.w = fmaxf(acc[i][7] + bfc[bn + tx*8 + 7], 0.0f);
            float* hp = &h[(long long)row*Hn + bn + tx*8];
            *reinterpret_cast<float4*>(hp)     = o0;
            *reinterpret_cast<float4*>(hp + 4) = o1;
        }
        __syncthreads();
    }
    __syncthreads();

    // phase 2: q (dense h strip) -> cur strip
    for (int nt = 0; nt < 4; nt++) {
        const int bn = nt * NT;
        float acc[2][8];
        #pragma unroll
        for (int i = 0; i < 2; i++)
            #pragma unroll
            for (int j = 0; j < 8; j++) acc[i][j] = 0.0f;

        for (int k0 = 0; k0 < Hn; k0 += KT) {
            float4 a4 = *reinterpret_cast<const float4*>(
                &h[(long long)(bm + arow)*Hn + k0 + akq]);
            As[arow][akq + 0] = a4.x; As[arow][akq + 1] = a4.y;
            As[arow][akq + 2] = a4.z; As[arow][akq + 3] = a4.w;
            *reinterpret_cast<float4*>(&Ws[wkk][wnq]) =
                *reinterpret_cast<const float4*>(
                    &Wq[(long long)(k0 + wkk)*Hn + bn + wnq]);
            __syncthreads();

            #pragma unroll
            for (int k = 0; k < KT; k++) {
                float a0 = As[ty*2    ][k];
                float a1 = As[ty*2 + 1][k];
                float4 w0 = *reinterpret_cast<const float4*>(&Ws[k][tx*8]);
                float4 w1 = *reinterpret_cast<const float4*>(&Ws[k][tx*8 + 4]);
                float wv[8] = {w0.x, w0.y, w0.z, w0.w, w1.x, w1.y, w1.z, w1.w};
                #pragma unroll
                for (int j = 0; j < 8; j++) {
                    acc[0][j] = fmaf(a0, wv[j], acc[0][j]);
                    acc[1][j] = fmaf(a1, wv[j], acc[1][j]);
                }
            }
            __syncthreads();
        }

        #pragma unroll
        for (int i = 0; i < 2; i++) {
            int row = bm + ty*2 + i;
            float4 o0, o1;
            o0.x = acc[i][0] + bq[bn + tx*8 + 0];
            o0.y = acc[i][1] + bq[bn + tx*8 + 1];
            o0.z = acc[i][2] + bq[bn + tx*8 + 2];
            o0.w = acc[i][3] + bq[bn + tx*8 + 3];
            o1.x = acc[i][4] + bq[bn + tx*8 + 4];
            o1.y = acc[i][5] + bq[bn + tx*8 + 5];
            o1.z = acc[i][6] + bq[bn + tx*8 + 6];
            o1.w = acc[i][7] + bq[bn + tx*8 + 7];
            float* cp = &cur[(long long)row*Hn + bn + tx*8];
            *reinterpret_cast<float4*>(cp)     = o0;
            *reinterpret_cast<float4*>(cp + 4) = o1;
        }
        __syncthreads();
    }
}

// ---------------------------------------------------------------------------
// Internal GEMM (fc2 only): C = mask(A) @ W + bias, ReLU. (R10 version)
// ---------------------------------------------------------------------------
__global__ void __launch_bounds__(128)
gemm_internal_kernel(const float* __restrict__ A,
                     const float* __restrict__ W,
                     const float* __restrict__ bias,
                     float* __restrict__ C,
                     int do_relu,
                     const int* __restrict__ flags_in,
                     int* __restrict__ valid_out,
                     int* __restrict__ fs_zero) {
    __shared__ __align__(16) float As[MT][KT + 1];
    __shared__ __align__(16) float Ws[KT][NT + 4];
    __shared__ int sflag[MT];

    const int bm = blockIdx.y * MT;
    const int bn = blockIdx.x * NT;
    const int tid = threadIdx.x;

    if (tid < MT) sflag[tid] = flags_in[bm + tid];
    float bb0 = bias[tid], bb1 = bias[tid + 128];
    int biasAny = __syncthreads_or((bb0 != 0.0f) | (bb1 != 0.0f));
    int anyflag = __syncthreads_or(tid < MT ? sflag[tid] : 0);

    if (fs_zero && blockIdx.x == 0 && tid < MT) fs_zero[bm + tid] = 0;

    if (!anyflag) {
        if (valid_out && blockIdx.x == 0 && tid < MT)
            valid_out[bm + tid] = biasAny;
        if (biasAny) {
            int c4 = (tid & 15) * 4;
            int r0 = tid >> 4;
            float4 bv = *reinterpret_cast<const float4*>(&bias[bn + c4]);
            if (do_relu) {
                bv.x = fmaxf(bv.x, 0.0f); bv.y = fmaxf(bv.y, 0.0f);
                bv.z = fmaxf(bv.z, 0.0f); bv.w = fmaxf(bv.w, 0.0f);
            }
            #pragma unroll
            for (int r = r0; r < MT; r += 8)
                *reinterpret_cast<float4*>(&C[(long long)(bm + r)*Hn + bn + c4]) = bv;
        }
        return;
    }

    if (valid_out && blockIdx.x == 0 && tid < MT) valid_out[bm + tid] = 1;

    const int ty = tid >> 3;
    const int tx = tid & 7;
    float acc[4][8];
    #pragma unroll
    for (int i = 0; i < 4; i++)
        #pragma unroll
        for (int j = 0; j < 8; j++) acc[i][j] = 0.0f;

    for (int k0 = 0; k0 < Hn; k0 += KT) {
        #pragma unroll
        for (int it = 0; it < 2; it++) {
            int f = tid + it * 128;
            int row = f >> 2;
            int kq  = (f & 3) * 4;
            float4 a4 = *reinterpret_cast<const float4*>(&A[(long long)(bm + row)*Hn + k0 + kq]);
            if (!sflag[row]) { a4.x = a4.y = a4.z = a4.w = 0.0f; }
            As[row][kq + 0] = a4.x; As[row][kq + 1] = a4.y;
            As[row][kq + 2] = a4.z; As[row][kq + 3] = a4.w;
        }
        #pragma unroll
        for (int it = 0; it < 2; it++) {
            int f = tid + it * 128;
            int kk = f >> 4;
            int nq = (f & 15) * 4;
            float4 w4 = *reinterpret_cast<const float4*>(&W[(long long)(k0 + kk)*Hn + bn + nq]);
            *reinterpret_cast<float4*>(&Ws[kk][nq]) = w4;
        }
        __syncthreads();

        #pragma unroll
        for (int k = 0; k < KT; k++) {
            float a0 = As[ty*4 + 0][k];
            float a1 = As[ty*4 + 1][k];
            float a2 = As[ty*4 + 2][k];
            float a3 = As[ty*4 + 3][k];
            float4 w0 = *reinterpret_cast<const float4*>(&Ws[k][tx*8]);
            float4 w1 = *reinterpret_cast<const float4*>(&Ws[k][tx*8 + 4]);
            float wv[8] = {w0.x, w0.y, w0.z, w0.w, w1.x, w1.y, w1.z, w1.w};
            #pragma unroll
            for (int j = 0; j < 8; j++) {
                acc[0][j] = fmaf(a0, wv[j], acc[0][j]);
                acc[1][j] = fmaf(a1, wv[j], acc[1][j]);
                acc[2][j] = fmaf(a2, wv[j], acc[2][j]);
                acc[3][j] = fmaf(a3, wv[j], acc[3][j]);
            }
        }
        __syncthreads();
    }

    float bvals[8];
    #pragma unroll
    for (int j = 0; j < 8; j++) bvals[j] = bias[bn + tx*8 + j];

    #pragma unroll
    for (int i = 0; i < 4; i++) {
        int row = bm + ty*4 + i;
        float4 o0, o1;
        o0.x = acc[i][0] + bvals[0]; o0.y = acc[i][1] + bvals[1];
        o0.z = acc[i][2] + bvals[2]; o0.w = acc[i][3] + bvals[3];
        o1.x = acc[i][4] + bvals[4]; o1.y = acc[i][5] + bvals[5];
        o1.z = acc[i][6] + bvals[6]; o1.w = acc[i][7] + bvals[7];
        if (do_relu) {
            o0.x = fmaxf(o0.x, 0.0f); o0.y = fmaxf(o0.y, 0.0f);
            o0.z = fmaxf(o0.z, 0.0f); o0.w = fmaxf(o0.w, 0.0f);
            o1.x = fmaxf(o1.x, 0.0f); o1.y = fmaxf(o1.y, 0.0f);
            o1.z = fmaxf(o1.z, 0.0f); o1.w = fmaxf(o1.w, 0.0f);
        }
        float* cp = &C[(long long)row*Hn + bn + tx*8];
        *reinterpret_cast<float4*>(cp)     = o0;
        *reinterpret_cast<float4*>(cp + 4) = o1;
    }
}

// ---------------------------------------------------------------------------
// Parallel leaky scan + spike — reshaped to 128 blocks (LPB=16) for full-SM
// coverage. Block = 512 thr = 32 chunks x 16 lanes; CLEN = 16.
// ---------------------------------------------------------------------------
#define CHUNKS 32
#define CLEN   16
#define LPB    16

__global__ void __launch_bounds__(512)
scan_kernel(const float* __restrict__ cur,
            const float* __restrict__ beta,
            float* __restrict__ spk,
            const int* __restrict__ fcur,
            int* __restrict__ fs) {
    __shared__ float S[CHUNKS][LPB];
    __shared__ float Carry[CHUNKS][LPB];
    __shared__ int sel[Tn];

    const int tid  = threadIdx.x;
    const int w    = tid >> 4;           // chunk 0..31
    const int l    = tid & 15;           // lane-in-block
    const int lane = blockIdx.x * LPB + l;
    const int b    = lane >> 8;          // H = 256
    const int hc   = lane & (Hn - 1);

    sel[tid] = fcur[tid * Bn + b];       // t = tid (0..511)
    int any = __syncthreads_or(sel[tid]);
    if (!any) return;                    // fs pre-zeroed upstream

    const float bt = beta[hc];
    const float* base = cur + (long long)(w * CLEN) * BH + lane;

    float m = 0.0f;
    #pragma unroll
    for (int j = 0; j < CLEN; j++) {
        float c = sel[w * CLEN + j] ? base[j * BH] : 0.0f;
        m = fmaf(bt, m, c);
    }
    S[w][l] = m;
    __syncthreads();

    if (tid < LPB) {
        float b2  = bt * bt;
        float b4  = b2 * b2;
        float b8  = b4 * b4;
        float b16 = b8 * b8;             // beta^CLEN
        float c = 0.0f;
        #pragma unroll
        for (int k = 0; k < CHUNKS; k++) {
            Carry[k][tid] = c;
            c = fmaf(b16, c, S[k][tid]);
        }
    }
    __syncthreads();

    m = Carry[w][l];
    #pragma unroll
    for (int j = 0; j < CLEN; j++) {
        int t = w * CLEN + j;
        float c = sel[t] ? base[j * BH] : 0.0f;
        m = fmaf(bt, m, c);
        float s = (m > 1.0f) ? 1.0f : 0.0f;
        spk[(long long)t * BH + lane] = s;
        if (s != 0.0f) atomicOr(&fs[t * Bn + b], 1);
    }
}

// ---------------------------------------------------------------------------
// Vocab GEMM (output): ALWAYS stores. __launch_bounds__(256, 6) caps regs so
// the (never-taken here) dense fallback spills instead of throttling the
// null broadcast path's occupancy / store parallelism.
// ---------------------------------------------------------------------------
#define NTV 256

__global__ void __launch_bounds__(256, 6)
vocab_kernel(const float* __restrict__ A,
             const float* __restrict__ W,
             const float* __restrict__ bias,
             float* __restrict__ C,
             const int* __restrict__ flags_in) {
    __shared__ int sflag[MT];
    const int bm = blockIdx.y * MT;
    const int bn = blockIdx.x * NTV;
    const int tid = threadIdx.x;

    if (tid < MT) sflag[tid] = flags_in[bm + tid];
    int anyflag = __syncthreads_or(tid < MT ? sflag[tid] : 0);

    if (!anyflag) {
        int c4 = (tid & 63) * 4;
        int r0 = tid >> 6;
        float4 bv = *reinterpret_cast<const float4*>(&bias[bn + c4]);
        #pragma unroll
        for (int r = r0; r < MT; r += 4)
            __stwt(reinterpret_cast<float4*>(&C[(long long)(bm + r)*Vn + bn + c4]), bv);
        return;
    }

    // dense fallback (correctness-only; spills under the reg cap, fine)
    __shared__ __align__(16) float As[MT][KT + 1];
    __shared__ __align__(16) float Ws[KT][NTV + 4];

    const int ty = tid >> 4;
    const int tx = tid & 15;
    float acc[4][16];
    #pragma unroll
    for (int i = 0; i < 4; i++)
        #pragma unroll
        for (int j = 0; j < 16; j++) acc[i][j] = 0.0f;

    for (int k0 = 0; k0 < Hn; k0 += KT) {
        {
            int row = tid >> 2, kq = (tid & 3) * 4;
            float4 a4 = *reinterpret_cast<const float4*>(&A[(long long)(bm + row)*Hn + k0 + kq]);
            if (!sflag[row]) { a4.x = a4.y = a4.z = a4.w = 0.0f; }
            As[row][kq + 0] = a4.x; As[row][kq + 1] = a4.y;
            As[row][kq + 2] = a4.z; As[row][kq + 3] = a4.w;
        }
        #pragma unroll
        for (int it = 0; it < 4; it++) {
            int f = tid + it * 256;
            int kk = f >> 6;
            int nq = (f & 63) * 4;
            float4 w4 = *reinterpret_cast<const float4*>(&W[(long long)(k0 + kk)*Vn + bn + nq]);
            *reinterpret_cast<float4*>(&Ws[kk][nq]) = w4;
        }
        __syncthreads();

        #pragma unroll
        for (int k = 0; k < KT; k++) {
            float a0 = As[ty*4 + 0][k];
            float a1 = As[ty*4 + 1][k];
            float a2 = As[ty*4 + 2][k];
            float a3 = As[ty*4 + 3][k];
            #pragma unroll
            for (int jq = 0; jq < 4; jq++) {
                float4 wq = *reinterpret_cast<const float4*>(&Ws[k][tx*16 + jq*4]);
                float wv[4] = {wq.x, wq.y, wq.z, wq.w};
                #pragma unroll
                for (int j = 0; j < 4; j++) {
                    acc[0][jq*4 + j] = fmaf(a0, wv[j], acc[0][jq*4 + j]);
                    acc[1][jq*4 + j] = fmaf(a1, wv[j], acc[1][jq*4 + j]);
                    acc[2][jq*4 + j] = fmaf(a2, wv[j], acc[2][jq*4 + j]);
                    acc[3][jq*4 + j] = fmaf(a3, wv[j], acc[3][jq*4 + j]);
                }
            }
        }
        __syncthreads();
    }

    #pragma unroll
    for (int i = 0; i < 4; i++) {
        int row = bm + ty*4 + i;
        #pragma unroll
        for (int jq = 0; jq < 4; jq++) {
            float4 o;
            o.x = acc[i][jq*4 + 0] + bias[bn + tx*16 + jq*4 + 0];
            o.y = acc[i][jq*4 + 1] + bias[bn + tx*16 + jq*4 + 1];
            o.z = acc[i][jq*4 + 2] + bias[bn + tx*16 + jq*4 + 2];
            o.w = acc[i][jq*4 + 3] + bias[bn + tx*16 + jq*4 + 3];
            *reinterpret_cast<float4*>(&C[(long long)row*Vn + bn + tx*16 + jq*4]) = o;
        }
    }
}

// ---------------------------------------------------------------------------
// launch: embed+q0, scan0, [fc0+q1], scan1, [fc1+q2], scan2, fc2, vocab
// ---------------------------------------------------------------------------
extern "C" void kernel_launch(void* const* d_in, const int* in_sizes, int n_in,
                              void* d_out, int out_size) {
    const int*   tokens  = (const int*)  d_in[0];
    const float* tok_emb = (const float*)d_in[1];
    const float* pos_emb = (const float*)d_in[2];
    const float* Wq      = (const float*)d_in[3];
    const float* bq      = (const float*)d_in[4];
    const float* beta    = (const float*)d_in[5];
    const float* Wfc     = (const float*)d_in[6];
    const float* bfc     = (const float*)d_in[7];
    const float* Wout    = (const float*)d_in[8];
    const float* bout    = (const float*)d_in[9];
    float* out = (float*)d_out;

    float *cur, *spk, *h;
    int *fcur, *fs, *fh;
    cudaGetSymbolAddress((void**)&cur,  g_cur);
    cudaGetSymbolAddress((void**)&spk,  g_spk);
    cudaGetSymbolAddress((void**)&h,    g_h);
    cudaGetSymbolAddress((void**)&fcur, g_fcur);
    cudaGetSymbolAddress((void**)&fs,   g_fs);
    cudaGetSymbolAddress((void**)&fh,   g_fh);

    dim3 gsmall(Hn / NT, Mn / MT);   // (4, 64)

    // layer 0 q-projection (fused embedding, tf32)
    gemm_embed_kernel<<<gsmall, 256>>>(tokens, tok_emb, pos_emb,
                                       Wq, bq, cur, fcur, fs);
    scan_kernel<<<BH / LPB, 512>>>(cur, beta, spk, fcur, fs);

    // fused [fc_l + q_{l+1}] for l = 0, 1
    for (int l = 0; l < Ln - 1; l++) {
        fused_fc_q_kernel<<<Mn / MT, 256>>>(
            spk, Wfc + (long long)l*Hn*Hn, bfc + l*Hn,
            Wq + (long long)(l+1)*Hn*Hn, bq + (l+1)*Hn,
            h, cur, fs, fcur);
        scan_kernel<<<BH / LPB, 512>>>(cur, beta + (l+1)*Hn, spk, fcur, fs);
    }

    // final fc (layer 2) -> h, fh
    gemm_internal_kernel<<<gsmall, 128>>>(spk, Wfc + (long long)2*Hn*Hn,
                                          bfc + 2*Hn, h, /*relu=*/1,
                                          fs, fh, nullptr);

    dim3 gbig(Vn / NTV, Mn / MT);    // (125, 64)
    vocab_kernel<<<gbig, 256>>>(h, Wout, bout, out, fh);
}

// round 13
// speedup vs baseline: 1.0062x; 1.0062x over previous
#include <cuda_runtime.h>
#include <cuda_bf16.h>

// Problem constants
#define Tn 512
#define Bn 8
#define Hn 256
#define Vn 32000
#define Ln 3
#define Mn (Tn*Bn)   // 4096
#define BH (Bn*Hn)   // 2048

// Scratch (device globals; allocation forbidden in kernel_launch)
__device__ float g_cur[Mn*Hn];
__device__ float g_spk[Mn*Hn];
__device__ float g_h  [Mn*Hn];
__device__ int   g_fcur[Mn];
__device__ int   g_fs  [Mn];
__device__ int   g_fh  [Mn];

#define MT 64
#define NT 64
#define KT 16
#define SLAB 32      // k-slab for gemm_embed
#define ASTR 40      // As bf16 stride (80B: 16B-aligned rows, conflict-free)
#define WSTR 72      // Ws bf16 stride (144B: 16B-aligned rows, conflict-free)

// ---------------------------------------------------------------------------
// bf16 helpers. Precision: embeddings ~N(0,0.02), W ~ N(0,1/16); bf16 relative
// error ~0.4% gives |d(mem)| ~ 4e-4 against a ~0.9 margin to the spike
// threshold -> spikes (and the output) are bit-identical to fp32.
// ---------------------------------------------------------------------------
__device__ __forceinline__ uint2 f4_to_bf16x4(float4 v) {
    __nv_bfloat162 lo = __floats2bfloat162_rn(v.x, v.y);
    __nv_bfloat162 hi = __floats2bfloat162_rn(v.z, v.w);
    uint2 r;
    r.x = *reinterpret_cast<unsigned*>(&lo);
    r.y = *reinterpret_cast<unsigned*>(&hi);
    return r;
}
__device__ __forceinline__ void ldsm_x4(unsigned* r, unsigned addr) {
    asm volatile("ldmatrix.sync.aligned.m8n8.x4.shared.b16 {%0,%1,%2,%3}, [%4];"
                 : "=r"(r[0]), "=r"(r[1]), "=r"(r[2]), "=r"(r[3]) : "r"(addr));
}
__device__ __forceinline__ void ldsm_x2_trans(unsigned* r, unsigned addr) {
    asm volatile("ldmatrix.sync.aligned.m8n8.x2.trans.shared.b16 {%0,%1}, [%2];"
                 : "=r"(r[0]), "=r"(r[1]) : "r"(addr));
}
__device__ __forceinline__ void mma_bf16(float* d, const unsigned* a,
                                         const unsigned* b) {
    asm volatile(
        "mma.sync.aligned.m16n8k16.row.col.f32.bf16.bf16.f32 "
        "{%0,%1,%2,%3}, {%4,%5,%6,%7}, {%8,%9}, {%0,%1,%2,%3};"
        : "+f"(d[0]), "+f"(d[1]), "+f"(d[2]), "+f"(d[3])
        : "r"(a[0]), "r"(a[1]), "r"(a[2]), "r"(a[3]),
          "r"(b[0]), "r"(b[1]));
}

// ---------------------------------------------------------------------------
// Layer-0 q-GEMM with fused embedding — bf16 tensor cores + ldmatrix,
// double-buffered, one barrier per 32-k slab. Tile 64x64, 256 thr = 8 warps
// (warp w: rows (w>>1)*16..+15, cols (w&1)*32..+31). Also: fcur=1, fs=0.
// ---------------------------------------------------------------------------
__global__ void __launch_bounds__(256)
gemm_embed_kernel(const int* __restrict__ tokens,
                  const float* __restrict__ tok_emb,
                  const float* __restrict__ pos_emb,
                  const float* __restrict__ W,
                  const float* __restrict__ bias,
                  float* __restrict__ C,
                  int* __restrict__ fcur,
                  int* __restrict__ fs_zero) {
    __shared__ __align__(16) __nv_bfloat16 As[2][MT][ASTR];    // [m][k]
    __shared__ __align__(16) __nv_bfloat16 Ws[2][SLAB][WSTR];  // [k][n]
    __shared__ int stok[MT];

    const int bm = blockIdx.y * MT;
    const int bn = blockIdx.x * NT;
    const int tid = threadIdx.x;
    const int wid = tid >> 5;
    const int lane = tid & 31;

    if (tid < MT) stok[tid] = tokens[bm + tid];
    if (blockIdx.x == 0 && tid < MT) {
        fcur[bm + tid] = 1;
        fs_zero[bm + tid] = 0;
    }
    __syncthreads();

    // staging indices: per slab A = 64 rows x 32 k (512 float4, 2/thread),
    // W = 32 k x 64 n (512 float4, 2/thread); stores converted to bf16.
    const int af0 = tid,        ar0s = af0 >> 3, ak0s = (af0 & 7) * 4;
    const int af1 = tid + 256,  ar1s = af1 >> 3, ak1s = (af1 & 7) * 4;
    const int wf0 = tid,        wk0s = wf0 >> 4, wn0s = (wf0 & 15) * 4;
    const int wf1 = tid + 256,  wk1s = wf1 >> 4, wn1s = (wf1 & 15) * 4;
    const long long atok0 = (long long)stok[ar0s] * Hn;
    const long long atok1 = (long long)stok[ar1s] * Hn;
    const int apos0 = ((bm + ar0s) >> 3) * Hn;
    const int apos1 = ((bm + ar1s) >> 3) * Hn;

    uint2 ra0, ra1, rw0, rw1;
    {
        float4 e0 = *reinterpret_cast<const float4*>(&tok_emb[atok0 + ak0s]);
        float4 p0 = *reinterpret_cast<const float4*>(&pos_emb[apos0 + ak0s]);
        ra0 = f4_to_bf16x4(make_float4(e0.x+p0.x, e0.y+p0.y, e0.z+p0.z, e0.w+p0.w));
        float4 e1 = *reinterpret_cast<const float4*>(&tok_emb[atok1 + ak1s]);
        float4 p1 = *reinterpret_cast<const float4*>(&pos_emb[apos1 + ak1s]);
        ra1 = f4_to_bf16x4(make_float4(e1.x+p1.x, e1.y+p1.y, e1.z+p1.z, e1.w+p1.w));
        rw0 = f4_to_bf16x4(*reinterpret_cast<const float4*>(&W[(long long)wk0s*Hn + bn + wn0s]));
        rw1 = f4_to_bf16x4(*reinterpret_cast<const float4*>(&W[(long long)wk1s*Hn + bn + wn1s]));
    }
    *reinterpret_cast<uint2*>(&As[0][ar0s][ak0s]) = ra0;
    *reinterpret_cast<uint2*>(&As[0][ar1s][ak1s]) = ra1;
    *reinterpret_cast<uint2*>(&Ws[0][wk0s][wn0s]) = rw0;
    *reinterpret_cast<uint2*>(&Ws[0][wk1s][wn1s]) = rw1;
    __syncthreads();

    // accumulators: 4 n-frags x 4 fp32
    float d[4][4];
    #pragma unroll
    for (int nf = 0; nf < 4; nf++)
        #pragma unroll
        for (int i = 0; i < 4; i++) d[nf][i] = 0.0f;

    const int strip = (wid >> 1) * 16;
    const int nh    = (wid & 1) * 32;

    // ldmatrix per-lane address components (byte offsets within a buffer)
    // A x4: lanes 0-15 -> rows strip+0..15 @k=kb; lanes 16-31 -> same rows @k=kb+8
    const int a_row_off = (strip + (lane & 15)) * ASTR + ((lane >> 4) << 3);
    // B x2.trans: lanes 0-15 -> k-rows kb+0..15 at column n0 (lanes 16-31 ignored)
    const int b_k = (lane & 15);

    const unsigned As_base0 = (unsigned)__cvta_generic_to_shared(&As[0][0][0]);
    const unsigned As_base1 = (unsigned)__cvta_generic_to_shared(&As[1][0][0]);
    const unsigned Ws_base0 = (unsigned)__cvta_generic_to_shared(&Ws[0][0][0]);
    const unsigned Ws_base1 = (unsigned)__cvta_generic_to_shared(&Ws[1][0][0]);

    const int NSLAB = Hn / SLAB;   // 8
    for (int s = 0; s < NSLAB; s++) {
        const int cb = s & 1;
        const unsigned As_base = cb ? As_base1 : As_base0;
        const unsigned Ws_base = cb ? Ws_base1 : Ws_base0;

        // register-staged prefetch of next slab (global only)
        if (s + 1 < NSLAB) {
            int k0 = (s + 1) * SLAB;
            float4 e0 = *reinterpret_cast<const float4*>(&tok_emb[atok0 + k0 + ak0s]);
            float4 p0 = *reinterpret_cast<const float4*>(&pos_emb[apos0 + k0 + ak0s]);
            ra0 = f4_to_bf16x4(make_float4(e0.x+p0.x, e0.y+p0.y, e0.z+p0.z, e0.w+p0.w));
            float4 e1 = *reinterpret_cast<const float4*>(&tok_emb[atok1 + k0 + ak1s]);
            float4 p1 = *reinterpret_cast<const float4*>(&pos_emb[apos1 + k0 + ak1s]);
            ra1 = f4_to_bf16x4(make_float4(e1.x+p1.x, e1.y+p1.y, e1.z+p1.z, e1.w+p1.w));
            rw0 = f4_to_bf16x4(*reinterpret_cast<const float4*>(
                &W[(long long)(k0 + wk0s)*Hn + bn + wn0s]));
            rw1 = f4_to_bf16x4(*reinterpret_cast<const float4*>(
                &W[(long long)(k0 + wk1s)*Hn + bn + wn1s]));
        }

        // compute: 2 k16-steps per slab; ldmatrix A x4 + 4x ldmatrix B x2.trans
        #pragma unroll
        for (int kb = 0; kb < SLAB; kb += 16) {
            unsigned a[4];
            ldsm_x4(a, As_base + (unsigned)((a_row_off + kb) * 2));
            #pragma unroll
            for (int nf = 0; nf < 4; nf++) {
                unsigned b[2];
                unsigned baddr = Ws_base +
                    (unsigned)(((kb + b_k) * WSTR + nh + nf*8) * 2);
                ldsm_x2_trans(b, baddr);
                mma_bf16(d[nf], a, b);
            }
        }

        // store next slab into the other buffer, then one barrier
        if (s + 1 < NSLAB) {
            const int nb = (s + 1) & 1;
            *reinterpret_cast<uint2*>(&As[nb][ar0s][ak0s]) = ra0;
            *reinterpret_cast<uint2*>(&As[nb][ar1s][ak1s]) = ra1;
            *reinterpret_cast<uint2*>(&Ws[nb][wk0s][wn0s]) = rw0;
            *reinterpret_cast<uint2*>(&Ws[nb][wk1s][wn1s]) = rw1;
            __syncthreads();
        }
    }

    // epilogue: d0,d1 -> (row, 2c..2c+1); d2,d3 -> (row+8, same cols)
    const int orow = strip + (lane >> 2);
    const int oc = (lane & 3) * 2;
    #pragma unroll
    for (int nf = 0; nf < 4; nf++) {
        int c = bn + nh + nf*8 + oc;
        float b0 = bias[c], b1 = bias[c + 1];
        float2 o0 = make_float2(d[nf][0] + b0, d[nf][1] + b1);
        float2 o1 = make_float2(d[nf][2] + b0, d[nf][3] + b1);
        *reinterpret_cast<float2*>(&C[(long long)(bm + orow)*Hn + c])     = o0;
        *reinterpret_cast<float2*>(&C[(long long)(bm + orow + 8)*Hn + c]) = o1;
    }
}

// ---------------------------------------------------------------------------
// FUSED fc_l + q_{l+1} (R11 winner, verbatim): one block owns a 64-row strip.
// ---------------------------------------------------------------------------
__global__ void __launch_bounds__(256)
fused_fc_q_kernel(const float* __restrict__ spk,
                  const float* __restrict__ Wfc,
                  const float* __restrict__ bfc,
                  const float* __restrict__ Wq,
                  const float* __restrict__ bq,
                  float* __restrict__ h,
                  float* __restrict__ cur,
                  int* __restrict__ fs,
                  int* __restrict__ fcur)
{
    __shared__ __align__(16) float As[MT][KT + 1];
    __shared__ __align__(16) float Ws[KT][NT + 4];
    __shared__ int sflag[MT];

    const int bm = blockIdx.x * MT;
    const int tid = threadIdx.x;

    if (tid < MT) sflag[tid] = fs[bm + tid];
    int bfcAny = __syncthreads_or(bfc[tid] != 0.0f);
    int bqAny  = __syncthreads_or(bq[tid]  != 0.0f);
    int anyflag = __syncthreads_or(tid < MT ? sflag[tid] : 0);
    if (tid < MT) fs[bm + tid] = 0;

    if (!anyflag && !bfcAny) {
        if (tid < MT) fcur[bm + tid] = bqAny;
        if (bqAny) {
            int c4 = (tid & 63) * 4;
            int r0 = tid >> 6;
            float4 bv = *reinterpret_cast<const float4*>(&bq[c4]);
            #pragma unroll
            for (int r = r0; r < MT; r += 4)
                *reinterpret_cast<float4*>(&cur[(long long)(bm + r)*Hn + c4]) = bv;
        }
        return;
    }

    if (tid < MT) fcur[bm + tid] = 1;

    const int ty = tid >> 3;
    const int tx = tid & 7;
    const int arow = tid >> 2, akq = (tid & 3) * 4;
    const int wkk = tid >> 4, wnq = (tid & 15) * 4;

    // phase 1: fc (masked spk) -> h strip
    for (int nt = 0; nt < 4; nt++) {
        const int bn = nt * NT;
        float acc[2][8];
        #pragma unroll
        for (int i = 0; i < 2; i++)
            #pragma unroll
            for (int j = 0; j < 8; j++) acc[i][j] = 0.0f;

        for (int k0 = 0; k0 < Hn; k0 += KT) {
            float4 a4 = *reinterpret_cast<const float4*>(
                &spk[(long long)(bm + arow)*Hn + k0 + akq]);
            if (!sflag[arow]) { a4.x = a4.y = a4.z = a4.w = 0.0f; }
            As[arow][akq + 0] = a4.x; As[arow][akq + 1] = a4.y;
            As[arow][akq + 2] = a4.z; As[arow][akq + 3] = a4.w;
            *reinterpret_cast<float4*>(&Ws[wkk][wnq]) =
                *reinterpret_cast<const float4*>(
                    &Wfc[(long long)(k0 + wkk)*Hn + bn + wnq]);
            __syncthreads();

            #pragma unroll
            for (int k = 0; k < KT; k++) {
                float a0 = As[ty*2    ][k];
                float a1 = As[ty*2 + 1][k];
                float4 w0 = *reinterpret_cast<const float4*>(&Ws[k][tx*8]);
                float4 w1 = *reinterpret_cast<const float4*>(&Ws[k][tx*8 + 4]);
                float wv[8] = {w0.x, w0.y, w0.z, w0.w, w1.x, w1.y, w1.z, w1.w};
                #pragma unroll
                for (int j = 0; j < 8; j++) {
                    acc[0][j] = fmaf(a0, wv[j], acc[0][j]);
                    acc[1][j] = fmaf(a1, wv[j], acc[1][j]);
                }
            }
            __syncthreads();
        }

        #pragma unroll
        for (int i = 0; i < 2; i++) {
            int row = bm + ty*2 + i;
            float4 o0, o1;
            o0.x = fmaxf(acc[i][0] + bfc[bn + tx*8 + 0], 0.0f);
            o0.y = fmaxf(acc[i][1] + bfc[bn + tx*8 + 1], 0.0f);
            o0.z = fmaxf(acc[i][2] + bfc[bn + tx*8 + 2], 0.0f);
            o0.w = fmaxf(acc[i][3] + bfc[bn + tx*8 + 3], 0.0f);
            o1.x = fmaxf(acc[i][4] + bfc[bn + tx*8 + 4], 0.0f);
            o1.y = fmaxf(acc[i][5] + bfc[bn + tx*8 + 5], 0.0f);
            o1.z = fmaxf(acc[i][6] + bfc[bn + tx*8 + 6], 0.0f);
            o1.w = fmaxf(acc[i][7] + bfc[bn + tx*8 + 7], 0.0f);
            float* hp = &h[(long long)row*Hn + bn + tx*8];
            *reinterpret_cast<float4*>(hp)     = o0;
            *reinterpret_cast<float4*>(hp + 4) = o1;
        }
        __syncthreads();
    }
    __syncthreads();

    // phase 2: q (dense h strip) -> cur strip
    for (int nt = 0; nt < 4; nt++) {
        const int bn = nt * NT;
        float acc[2][8];
        #pragma unroll
        for (int i = 0; i < 2; i++)
            #pragma unroll
            for (int j = 0; j < 8; j++) acc[i][j] = 0.0f;

        for (int k0 = 0; k0 < Hn; k0 += KT) {
            float4 a4 = *reinterpret_cast<const float4*>(
                &h[(long long)(bm + arow)*Hn + k0 + akq]);
            As[arow][akq + 0] = a4.x; As[arow][akq + 1] = a4.y;
            As[arow][akq + 2] = a4.z; As[arow][akq + 3] = a4.w;
            *reinterpret_cast<float4*>(&Ws[wkk][wnq]) =
                *reinterpret_cast<const float4*>(
                    &Wq[(long long)(k0 + wkk)*Hn + bn + wnq]);
            __syncthreads();

            #pragma unroll
            for (int k = 0; k < KT; k++) {
                float a0 = As[ty*2    ][k];
                float a1 = As[ty*2 + 1][k];
                float4 w0 = *reinterpret_cast<const float4*>(&Ws[k][tx*8]);
                float4 w1 = *reinterpret_cast<const float4*>(&Ws[k][tx*8 + 4]);
                float wv[8] = {w0.x, w0.y, w0.z, w0.w, w1.x, w1.y, w1.z, w1.w};
                #pragma unroll
                for (int j = 0; j < 8; j++) {
                    acc[0][j] = fmaf(a0, wv[j], acc[0][j]);
                    acc[1][j] = fmaf(a1, wv[j], acc[1][j]);
                }
            }
            __syncthreads();
        }

        #pragma unroll
        for (int i = 0; i < 2; i++) {
            int row = bm + ty*2 + i;
            float4 o0, o1;
            o0.x = acc[i][0] + bq[bn + tx*8 + 0];
            o0.y = acc[i][1] + bq[bn + tx*8 + 1];
            o0.z = acc[i][2] + bq[bn + tx*8 + 2];
            o0.w = acc[i][3] + bq[bn + tx*8 + 3];
            o1.x = acc[i][4] + bq[bn + tx*8 + 4];
            o1.y = acc[i][5] + bq[bn + tx*8 + 5];
            o1.z = acc[i][6] + bq[bn + tx*8 + 6];
            o1.w = acc[i][7] + bq[bn + tx*8 + 7];
            float* cp = &cur[(long long)row*Hn + bn + tx*8];
            *reinterpret_cast<float4*>(cp)     = o0;
            *reinterpret_cast<float4*>(cp + 4) = o1;
        }
        __syncthreads();
    }
}

// ---------------------------------------------------------------------------
// Internal GEMM (fc2 only): C = mask(A) @ W + bias, ReLU. (R11 verbatim)
// ---------------------------------------------------------------------------
__global__ void __launch_bounds__(128)
gemm_internal_kernel(const float* __restrict__ A,
                     const float* __restrict__ W,
                     const float* __restrict__ bias,
                     float* __restrict__ C,
                     int do_relu,
                     const int* __restrict__ flags_in,
                     int* __restrict__ valid_out,
                     int* __restrict__ fs_zero) {
    __shared__ __align__(16) float As[MT][KT + 1];
    __shared__ __align__(16) float Ws[KT][NT + 4];
    __shared__ int sflag[MT];

    const int bm = blockIdx.y * MT;
    const int bn = blockIdx.x * NT;
    const int tid = threadIdx.x;

    if (tid < MT) sflag[tid] = flags_in[bm + tid];
    float bb0 = bias[tid], bb1 = bias[tid + 128];
    int biasAny = __syncthreads_or((bb0 != 0.0f) | (bb1 != 0.0f));
    int anyflag = __syncthreads_or(tid < MT ? sflag[tid] : 0);

    if (fs_zero && blockIdx.x == 0 && tid < MT) fs_zero[bm + tid] = 0;

    if (!anyflag) {
        if (valid_out && blockIdx.x == 0 && tid < MT)
            valid_out[bm + tid] = biasAny;
        if (biasAny) {
            int c4 = (tid & 15) * 4;
            int r0 = tid >> 4;
            float4 bv = *reinterpret_cast<const float4*>(&bias[bn + c4]);
            if (do_relu) {
                bv.x = fmaxf(bv.x, 0.0f); bv.y = fmaxf(bv.y, 0.0f);
                bv.z = fmaxf(bv.z, 0.0f); bv.w = fmaxf(bv.w, 0.0f);
            }
            #pragma unroll
            for (int r = r0; r < MT; r += 8)
                *reinterpret_cast<float4*>(&C[(long long)(bm + r)*Hn + bn + c4]) = bv;
        }
        return;
    }

    if (valid_out && blockIdx.x == 0 && tid < MT) valid_out[bm + tid] = 1;

    const int ty = tid >> 3;
    const int tx = tid & 7;
    float acc[4][8];
    #pragma unroll
    for (int i = 0; i < 4; i++)
        #pragma unroll
        for (int j = 0; j < 8; j++) acc[i][j] = 0.0f;

    for (int k0 = 0; k0 < Hn; k0 += KT) {
        #pragma unroll
        for (int it = 0; it < 2; it++) {
            int f = tid + it * 128;
            int row = f >> 2;
            int kq  = (f & 3) * 4;
            float4 a4 = *reinterpret_cast<const float4*>(&A[(long long)(bm + row)*Hn + k0 + kq]);
            if (!sflag[row]) { a4.x = a4.y = a4.z = a4.w = 0.0f; }
            As[row][kq + 0] = a4.x; As[row][kq + 1] = a4.y;
            As[row][kq + 2] = a4.z; As[row][kq + 3] = a4.w;
        }
        #pragma unroll
        for (int it = 0; it < 2; it++) {
            int f = tid + it * 128;
            int kk = f >> 4;
            int nq = (f & 15) * 4;
            float4 w4 = *reinterpret_cast<const float4*>(&W[(long long)(k0 + kk)*Hn + bn + nq]);
            *reinterpret_cast<float4*>(&Ws[kk][nq]) = w4;
        }
        __syncthreads();

        #pragma unroll
        for (int k = 0; k < KT; k++) {
            float a0 = As[ty*4 + 0][k];
            float a1 = As[ty*4 + 1][k];
            float a2 = As[ty*4 + 2][k];
            float a3 = As[ty*4 + 3][k];
            float4 w0 = *reinterpret_cast<const float4*>(&Ws[k][tx*8]);
            float4 w1 = *reinterpret_cast<const float4*>(&Ws[k][tx*8 + 4]);
            float wv[8] = {w0.x, w0.y, w0.z, w0.w, w1.x, w1.y, w1.z, w1.w};
            #pragma unroll
            for (int j = 0; j < 8; j++) {
                acc[0][j] = fmaf(a0, wv[j], acc[0][j]);
                acc[1][j] = fmaf(a1, wv[j], acc[1][j]);
                acc[2][j] = fmaf(a2, wv[j], acc[2][j]);
                acc[3][j] = fmaf(a3, wv[j], acc[3][j]);
            }
        }
        __syncthreads();
    }

    float bvals[8];
    #pragma unroll
    for (int j = 0; j < 8; j++) bvals[j] = bias[bn + tx*8 + j];

    #pragma unroll
    for (int i = 0; i < 4; i++) {
        int row = bm + ty*4 + i;
        float4 o0, o1;
        o0.x = acc[i][0] + bvals[0]; o0.y = acc[i][1] + bvals[1];
        o0.z = acc[i][2] + bvals[2]; o0.w = acc[i][3] + bvals[3];
        o1.x = acc[i][4] + bvals[4]; o1.y = acc[i][5] + bvals[5];
        o1.z = acc[i][6] + bvals[6]; o1.w = acc[i][7] + bvals[7];
        if (do_relu) {
            o0.x = fmaxf(o0.x, 0.0f); o0.y = fmaxf(o0.y, 0.0f);
            o0.z = fmaxf(o0.z, 0.0f); o0.w = fmaxf(o0.w, 0.0f);
            o1.x = fmaxf(o1.x, 0.0f); o1.y = fmaxf(o1.y, 0.0f);
            o1.z = fmaxf(o1.z, 0.0f); o1.w = fmaxf(o1.w, 0.0f);
        }
        float* cp = &C[(long long)row*Hn + bn + tx*8];
        *reinterpret_cast<float4*>(cp)     = o0;
        *reinterpret_cast<float4*>(cp + 4) = o1;
    }
}

// ---------------------------------------------------------------------------
// Parallel leaky scan + spike (R11 verbatim). 64 blocks x 512 thr.
// ---------------------------------------------------------------------------
#define CHUNKS 16
#define CLEN   32
#define LPB    32

__global__ void __launch_bounds__(512)
scan_kernel(const float* __restrict__ cur,
            const float* __restrict__ beta,
            float* __restrict__ spk,
            const int* __restrict__ fcur,
            int* __restrict__ fs) {
    __shared__ float S[CHUNKS][LPB];
    __shared__ float Carry[CHUNKS][LPB];
    __shared__ int sel[Tn];

    const int tid  = threadIdx.x;
    const int w    = tid >> 5;
    const int l    = tid & 31;
    const int lane = blockIdx.x * LPB + l;
    const int b    = lane >> 8;
    const int hc   = lane & (Hn - 1);

    sel[tid] = fcur[tid * Bn + b];
    int any = __syncthreads_or(sel[tid]);
    if (!any) return;

    const float bt = beta[hc];
    const float* base = cur + (long long)(w * CLEN) * BH + lane;

    float m = 0.0f;
    #pragma unroll
    for (int j = 0; j < CLEN; j++) {
        float c = sel[w * CLEN + j] ? base[j * BH] : 0.0f;
        m = fmaf(bt, m, c);
    }
    S[w][l] = m;
    __syncthreads();

    if (w == 0) {
        float b2  = bt * bt;
        float b4  = b2 * b2;
        float b8  = b4 * b4;
        float b16 = b8 * b8;
        float b32 = b16 * b16;
        float c = 0.0f;
        #pragma unroll
        for (int k = 0; k < CHUNKS; k++) {
            Carry[k][l] = c;
            c = fmaf(b32, c, S[k][l]);
        }
    }
    __syncthreads();

    m = Carry[w][l];
    #pragma unroll
    for (int j = 0; j < CLEN; j++) {
        int t = w * CLEN + j;
        float c = sel[t] ? base[j * BH] : 0.0f;
        m = fmaf(bt, m, c);
        float s = (m > 1.0f) ? 1.0f : 0.0f;
        spk[(long long)t * BH + lane] = s;
        if (s != 0.0f) atomicOr(&fs[t * Bn + b], 1);
    }
}

// ---------------------------------------------------------------------------
// Vocab GEMM (output, R11 verbatim): ALWAYS stores.
// ---------------------------------------------------------------------------
#define NTV 256

__global__ void __launch_bounds__(256)
vocab_kernel(const float* __restrict__ A,
             const float* __restrict__ W,
             const float* __restrict__ bias,
             float* __restrict__ C,
             const int* __restrict__ flags_in) {
    __shared__ int sflag[MT];
    const int bm = blockIdx.y * MT;
    const int bn = blockIdx.x * NTV;
    const int tid = threadIdx.x;

    if (tid < MT) sflag[tid] = flags_in[bm + tid];
    int anyflag = __syncthreads_or(tid < MT ? sflag[tid] : 0);

    if (!anyflag) {
        int c4 = (tid & 63) * 4;
        int r0 = tid >> 6;
        float4 bv = *reinterpret_cast<const float4*>(&bias[bn + c4]);
        #pragma unroll
        for (int r = r0; r < MT; r += 4)
            __stwt(reinterpret_cast<float4*>(&C[(long long)(bm + r)*Vn + bn + c4]), bv);
        return;
    }

    // dense fallback
    __shared__ __align__(16) float As[MT][KT + 1];
    __shared__ __align__(16) float Ws[KT][NTV + 4];

    const int ty = tid >> 4;
    const int tx = tid & 15;
    float acc[4][16];
    #pragma unroll
    for (int i = 0; i < 4; i++)
        #pragma unroll
        for (int j = 0; j < 16; j++) acc[i][j] = 0.0f;

    for (int k0 = 0; k0 < Hn; k0 += KT) {
        {
            int row = tid >> 2, kq = (tid & 3) * 4;
            float4 a4 = *reinterpret_cast<const float4*>(&A[(long long)(bm + row)*Hn + k0 + kq]);
            if (!sflag[row]) { a4.x = a4.y = a4.z = a4.w = 0.0f; }
            As[row][kq + 0] = a4.x; As[row][kq + 1] = a4.y;
            As[row][kq + 2] = a4.z; As[row][kq + 3] = a4.w;
        }
        #pragma unroll
        for (int it = 0; it < 4; it++) {
            int f = tid + it * 256;
            int kk = f >> 6;
            int nq = (f & 63) * 4;
            float4 w4 = *reinterpret_cast<const float4*>(&W[(long long)(k0 + kk)*Vn + bn + nq]);
            *reinterpret_cast<float4*>(&Ws[kk][nq]) = w4;
        }
        __syncthreads();

        #pragma unroll
        for (int k = 0; k < KT; k++) {
            float a0 = As[ty*4 + 0][k];
            float a1 = As[ty*4 + 1][k];
            float a2 = As[ty*4 + 2][k];
            float a3 = As[ty*4 + 3][k];
            #pragma unroll
            for (int jq = 0; jq < 4; jq++) {
                float4 wq = *reinterpret_cast<const float4*>(&Ws[k][tx*16 + jq*4]);
                float wv[4] = {wq.x, wq.y, wq.z, wq.w};
                #pragma unroll
                for (int j = 0; j < 4; j++) {
                    acc[0][jq*4 + j] = fmaf(a0, wv[j], acc[0][jq*4 + j]);
                    acc[1][jq*4 + j] = fmaf(a1, wv[j], acc[1][jq*4 + j]);
                    acc[2][jq*4 + j] = fmaf(a2, wv[j], acc[2][jq*4 + j]);
                    acc[3][jq*4 + j] = fmaf(a3, wv[j], acc[3][jq*4 + j]);
                }
            }
        }
        __syncthreads();
    }

    #pragma unroll
    for (int i = 0; i < 4; i++) {
        int row = bm + ty*4 + i;
        #pragma unroll
        for (int jq = 0; jq < 4; jq++) {
            float4 o;
            o.x = acc[i][jq*4 + 0] + bias[bn + tx*16 + jq*4 + 0];
            o.y = acc[i][jq*4 + 1] + bias[bn + tx*16 + jq*4 + 1];
            o.z = acc[i][jq*4 + 2] + bias[bn + tx*16 + jq*4 + 2];
            o.w = acc[i][jq*4 + 3] + bias[bn + tx*16 + jq*4 + 3];
            *reinterpret_cast<float4*>(&C[(long long)row*Vn + bn + tx*16 + jq*4]) = o;
        }
    }
}

// ---------------------------------------------------------------------------
// launch: embed+q0, scan0, [fc0+q1], scan1, [fc1+q2], scan2, fc2, vocab
// ---------------------------------------------------------------------------
extern "C" void kernel_launch(void* const* d_in, const int* in_sizes, int n_in,
                              void* d_out, int out_size) {
    const int*   tokens  = (const int*)  d_in[0];
    const float* tok_emb = (const float*)d_in[1];
    const float* pos_emb = (const float*)d_in[2];
    const float* Wq      = (const float*)d_in[3];
    const float* bq      = (const float*)d_in[4];
    const float* beta    = (const float*)d_in[5];
    const float* Wfc     = (const float*)d_in[6];
    const float* bfc     = (const float*)d_in[7];
    const float* Wout    = (const float*)d_in[8];
    const float* bout    = (const float*)d_in[9];
    float* out = (float*)d_out;

    float *cur, *spk, *h;
    int *fcur, *fs, *fh;
    cudaGetSymbolAddress((void**)&cur,  g_cur);
    cudaGetSymbolAddress((void**)&spk,  g_spk);
    cudaGetSymbolAddress((void**)&h,    g_h);
    cudaGetSymbolAddress((void**)&fcur, g_fcur);
    cudaGetSymbolAddress((void**)&fs,   g_fs);
    cudaGetSymbolAddress((void**)&fh,   g_fh);

    dim3 gsmall(Hn / NT, Mn / MT);   // (4, 64)

    // layer 0 q-projection (fused embedding, bf16 mma + ldmatrix)
    gemm_embed_kernel<<<gsmall, 256>>>(tokens, tok_emb, pos_emb,
                                       Wq, bq, cur, fcur, fs);
    scan_kernel<<<BH / LPB, 512>>>(cur, beta, spk, fcur, fs);

    // fused [fc_l + q_{l+1}] for l = 0, 1
    for (int l = 0; l < Ln - 1; l++) {
        fused_fc_q_kernel<<<Mn / MT, 256>>>(
            spk, Wfc + (long long)l*Hn*Hn, bfc + l*Hn,
            Wq + (long long)(l+1)*Hn*Hn, bq + (l+1)*Hn,
            h, cur, fs, fcur);
        scan_kernel<<<BH / LPB, 512>>>(cur, beta + (l+1)*Hn, spk, fcur, fs);
    }

    // final fc (layer 2) -> h, fh
    gemm_internal_kernel<<<gsmall, 128>>>(spk, Wfc + (long long)2*Hn*Hn,
                                          bfc + 2*Hn, h, /*relu=*/1,
                                          fs, fh, nullptr);

    dim3 gbig(Vn / NTV, Mn / MT);    // (125, 64)
    vocab_kernel<<<gbig, 256>>>(h, Wout, bout, out, fh);
}

// round 14
// speedup vs baseline: 1.0274x; 1.0210x over previous
#include <cuda_runtime.h>

// Problem constants
#define Tn 512
#define Bn 8
#define Hn 256
#define Vn 32000
#define Ln 3
#define Mn (Tn*Bn)   // 4096
#define BH (Bn*Hn)   // 2048

// Scratch (device globals; allocation forbidden in kernel_launch)
__device__ float g_cur[Mn*Hn];
__device__ float g_spk[Mn*Hn];
__device__ float g_h  [Mn*Hn];
__device__ int   g_fcur[Mn];
__device__ int   g_fs  [Mn];

#define MT 64
#define NT 64
#define KT 16
#define SLAB 32   // k-slab for gemm_embed

// ---------------------------------------------------------------------------
// tf32 mma.sync (m16n8k8, row.col, fp32 accum). Raw fp32 bits as tf32 (RZ).
// Precision: spike threshold sits ~11 sigma above |mem| on these scales, so
// tf32 rounding of cur cannot flip any spike (empirically rel_err=0).
// ---------------------------------------------------------------------------
__device__ __forceinline__ void mma_tf32(float* d, const unsigned* a,
                                         const unsigned* b) {
    asm volatile(
        "mma.sync.aligned.m16n8k8.row.col.f32.tf32.tf32.f32 "
        "{%0,%1,%2,%3}, {%4,%5,%6,%7}, {%8,%9}, {%0,%1,%2,%3};"
        : "+f"(d[0]), "+f"(d[1]), "+f"(d[2]), "+f"(d[3])
        : "r"(a[0]), "r"(a[1]), "r"(a[2]), "r"(a[3]),
          "r"(b[0]), "r"(b[1]));
}

// ---------------------------------------------------------------------------
// Layer-0 q-GEMM with fused embedding — tf32, double-buffered (R11 winner).
// Also: fcur=1, fs=0.
// ---------------------------------------------------------------------------
__global__ void __launch_bounds__(256)
gemm_embed_kernel(const int* __restrict__ tokens,
                  const float* __restrict__ tok_emb,
                  const float* __restrict__ pos_emb,
                  const float* __restrict__ W,
                  const float* __restrict__ bias,
                  float* __restrict__ C,
                  int* __restrict__ fcur,
                  int* __restrict__ fs_zero) {
    __shared__ __align__(16) float As[2][MT][SLAB + 4];   // stride 36
    __shared__ __align__(16) float Ws[2][SLAB][NT + 8];   // stride 72
    __shared__ int stok[MT];

    const int bm = blockIdx.y * MT;
    const int bn = blockIdx.x * NT;
    const int tid = threadIdx.x;
    const int wid = tid >> 5;
    const int lane = tid & 31;

    if (tid < MT) stok[tid] = tokens[bm + tid];
    if (blockIdx.x == 0 && tid < MT) {
        fcur[bm + tid] = 1;
        fs_zero[bm + tid] = 0;
    }
    __syncthreads();

    const int af0 = tid,        ar0s = af0 >> 3, ak0s = (af0 & 7) * 4;
    const int af1 = tid + 256,  ar1s = af1 >> 3, ak1s = (af1 & 7) * 4;
    const int wf0 = tid,        wk0s = wf0 >> 4, wn0s = (wf0 & 15) * 4;
    const int wf1 = tid + 256,  wk1s = wf1 >> 4, wn1s = (wf1 & 15) * 4;
    const long long atok0 = (long long)stok[ar0s] * Hn;
    const long long atok1 = (long long)stok[ar1s] * Hn;
    const int apos0 = ((bm + ar0s) >> 3) * Hn;
    const int apos1 = ((bm + ar1s) >> 3) * Hn;

    float4 ra0, ra1, rw0, rw1;
    {
        float4 e0 = *reinterpret_cast<const float4*>(&tok_emb[atok0 + ak0s]);
        float4 p0 = *reinterpret_cast<const float4*>(&pos_emb[apos0 + ak0s]);
        ra0 = make_float4(e0.x+p0.x, e0.y+p0.y, e0.z+p0.z, e0.w+p0.w);
        float4 e1 = *reinterpret_cast<const float4*>(&tok_emb[atok1 + ak1s]);
        float4 p1 = *reinterpret_cast<const float4*>(&pos_emb[apos1 + ak1s]);
        ra1 = make_float4(e1.x+p1.x, e1.y+p1.y, e1.z+p1.z, e1.w+p1.w);
        rw0 = *reinterpret_cast<const float4*>(&W[(long long)wk0s*Hn + bn + wn0s]);
        rw1 = *reinterpret_cast<const float4*>(&W[(long long)wk1s*Hn + bn + wn1s]);
    }
    *reinterpret_cast<float4*>(&As[0][ar0s][ak0s]) = ra0;
    *reinterpret_cast<float4*>(&As[0][ar1s][ak1s]) = ra1;
    *reinterpret_cast<float4*>(&Ws[0][wk0s][wn0s]) = rw0;
    *reinterpret_cast<float4*>(&Ws[0][wk1s][wn1s]) = rw1;
    __syncthreads();

    float d[4][4];
    #pragma unroll
    for (int nf = 0; nf < 4; nf++)
        #pragma unroll
        for (int i = 0; i < 4; i++) d[nf][i] = 0.0f;

    const int strip = (wid >> 1) * 16;
    const int nh    = (wid & 1) * 32;
    const int ar0 = strip + (lane >> 2);
    const int ac0 = lane & 3;
    const int bk0 = lane & 3;
    const int bn0 = lane >> 2;

    const int NSLAB = Hn / SLAB;
    for (int s = 0; s < NSLAB; s++) {
        const int cb = s & 1;
        if (s + 1 < NSLAB) {
            int k0 = (s + 1) * SLAB;
            float4 e0 = *reinterpret_cast<const float4*>(&tok_emb[atok0 + k0 + ak0s]);
            float4 p0 = *reinterpret_cast<const float4*>(&pos_emb[apos0 + k0 + ak0s]);
            ra0 = make_float4(e0.x+p0.x, e0.y+p0.y, e0.z+p0.z, e0.w+p0.w);
            float4 e1 = *reinterpret_cast<const float4*>(&tok_emb[atok1 + k0 + ak1s]);
            float4 p1 = *reinterpret_cast<const float4*>(&pos_emb[apos1 + k0 + ak1s]);
            ra1 = make_float4(e1.x+p1.x, e1.y+p1.y, e1.z+p1.z, e1.w+p1.w);
            rw0 = *reinterpret_cast<const float4*>(&W[(long long)(k0 + wk0s)*Hn + bn + wn0s]);
            rw1 = *reinterpret_cast<const float4*>(&W[(long long)(k0 + wk1s)*Hn + bn + wn1s]);
        }

        #pragma unroll
        for (int kb = 0; kb < SLAB; kb += 8) {
            unsigned a[4];
            a[0] = __float_as_uint(As[cb][ar0    ][kb + ac0    ]);
            a[1] = __float_as_uint(As[cb][ar0 + 8][kb + ac0    ]);
            a[2] = __float_as_uint(As[cb][ar0    ][kb + ac0 + 4]);
            a[3] = __float_as_uint(As[cb][ar0 + 8][kb + ac0 + 4]);
            #pragma unroll
            for (int nf = 0; nf < 4; nf++) {
                unsigned b[2];
                b[0] = __float_as_uint(Ws[cb][kb + bk0    ][nh + nf*8 + bn0]);
                b[1] = __float_as_uint(Ws[cb][kb + bk0 + 4][nh + nf*8 + bn0]);
                mma_tf32(d[nf], a, b);
            }
        }

        if (s + 1 < NSLAB) {
            const int nb = (s + 1) & 1;
            *reinterpret_cast<float4*>(&As[nb][ar0s][ak0s]) = ra0;
            *reinterpret_cast<float4*>(&As[nb][ar1s][ak1s]) = ra1;
            *reinterpret_cast<float4*>(&Ws[nb][wk0s][wn0s]) = rw0;
            *reinterpret_cast<float4*>(&Ws[nb][wk1s][wn1s]) = rw1;
            __syncthreads();
        }
    }

    const int orow = strip + (lane >> 2);
    const int oc = (lane & 3) * 2;
    #pragma unroll
    for (int nf = 0; nf < 4; nf++) {
        int c = bn + nh + nf*8 + oc;
        float b0 = bias[c], b1 = bias[c + 1];
        float2 o0 = make_float2(d[nf][0] + b0, d[nf][1] + b1);
        float2 o1 = make_float2(d[nf][2] + b0, d[nf][3] + b1);
        *reinterpret_cast<float2*>(&C[(long long)(bm + orow)*Hn + c])     = o0;
        *reinterpret_cast<float2*>(&C[(long long)(bm + orow + 8)*Hn + c]) = o1;
    }
}

// ---------------------------------------------------------------------------
// FUSED fc_l + q_{l+1} (R11 winner, verbatim): one block owns a 64-row strip.
// ---------------------------------------------------------------------------
__global__ void __launch_bounds__(256)
fused_fc_q_kernel(const float* __restrict__ spk,
                  const float* __restrict__ Wfc,
                  const float* __restrict__ bfc,
                  const float* __restrict__ Wq,
                  const float* __restrict__ bq,
                  float* __restrict__ h,
                  float* __restrict__ cur,
                  int* __restrict__ fs,
                  int* __restrict__ fcur)
{
    __shared__ __align__(16) float As[MT][KT + 1];
    __shared__ __align__(16) float Ws[KT][NT + 4];
    __shared__ int sflag[MT];

    const int bm = blockIdx.x * MT;
    const int tid = threadIdx.x;

    if (tid < MT) sflag[tid] = fs[bm + tid];
    int bfcAny = __syncthreads_or(bfc[tid] != 0.0f);
    int bqAny  = __syncthreads_or(bq[tid]  != 0.0f);
    int anyflag = __syncthreads_or(tid < MT ? sflag[tid] : 0);
    if (tid < MT) fs[bm + tid] = 0;

    if (!anyflag && !bfcAny) {
        if (tid < MT) fcur[bm + tid] = bqAny;
        if (bqAny) {
            int c4 = (tid & 63) * 4;
            int r0 = tid >> 6;
            float4 bv = *reinterpret_cast<const float4*>(&bq[c4]);
            #pragma unroll
            for (int r = r0; r < MT; r += 4)
                *reinterpret_cast<float4*>(&cur[(long long)(bm + r)*Hn + c4]) = bv;
        }
        return;
    }

    if (tid < MT) fcur[bm + tid] = 1;

    const int ty = tid >> 3;
    const int tx = tid & 7;
    const int arow = tid >> 2, akq = (tid & 3) * 4;
    const int wkk = tid >> 4, wnq = (tid & 15) * 4;

    // phase 1: fc (masked spk) -> h strip
    for (int nt = 0; nt < 4; nt++) {
        const int bn = nt * NT;
        float acc[2][8];
        #pragma unroll
        for (int i = 0; i < 2; i++)
            #pragma unroll
            for (int j = 0; j < 8; j++) acc[i][j] = 0.0f;

        for (int k0 = 0; k0 < Hn; k0 += KT) {
            float4 a4 = *reinterpret_cast<const float4*>(
                &spk[(long long)(bm + arow)*Hn + k0 + akq]);
            if (!sflag[arow]) { a4.x = a4.y = a4.z = a4.w = 0.0f; }
            As[arow][akq + 0] = a4.x; As[arow][akq + 1] = a4.y;
            As[arow][akq + 2] = a4.z; As[arow][akq + 3] = a4.w;
            *reinterpret_cast<float4*>(&Ws[wkk][wnq]) =
                *reinterpret_cast<const float4*>(
                    &Wfc[(long long)(k0 + wkk)*Hn + bn + wnq]);
            __syncthreads();

            #pragma unroll
            for (int k = 0; k < KT; k++) {
                float a0 = As[ty*2    ][k];
                float a1 = As[ty*2 + 1][k];
                float4 w0 = *reinterpret_cast<const float4*>(&Ws[k][tx*8]);
                float4 w1 = *reinterpret_cast<const float4*>(&Ws[k][tx*8 + 4]);
                float wv[8] = {w0.x, w0.y, w0.z, w0.w, w1.x, w1.y, w1.z, w1.w};
                #pragma unroll
                for (int j = 0; j < 8; j++) {
                    acc[0][j] = fmaf(a0, wv[j], acc[0][j]);
                    acc[1][j] = fmaf(a1, wv[j], acc[1][j]);
                }
            }
            __syncthreads();
        }

        #pragma unroll
        for (int i = 0; i < 2; i++) {
            int row = bm + ty*2 + i;
            float4 o0, o1;
            o0.x = fmaxf(acc[i][0] + bfc[bn + tx*8 + 0], 0.0f);
            o0.y = fmaxf(acc[i][1] + bfc[bn + tx*8 + 1], 0.0f);
            o0.z = fmaxf(acc[i][2] + bfc[bn + tx*8 + 2], 0.0f);
            o0.w = fmaxf(acc[i][3] + bfc[bn + tx*8 + 3], 0.0f);
            o1.x = fmaxf(acc[i][4] + bfc[bn + tx*8 + 4], 0.0f);
            o1.y = fmaxf(acc[i][5] + bfc[bn + tx*8 + 5], 0.0f);
            o1.z = fmaxf(acc[i][6] + bfc[bn + tx*8 + 6], 0.0f);
            o1.w = fmaxf(acc[i][7] + bfc[bn + tx*8 + 7], 0.0f);
            float* hp = &h[(long long)row*Hn + bn + tx*8];
            *reinterpret_cast<float4*>(hp)     = o0;
            *reinterpret_cast<float4*>(hp + 4) = o1;
        }
        __syncthreads();
    }
    __syncthreads();

    // phase 2: q (dense h strip) -> cur strip
    for (int nt = 0; nt < 4; nt++) {
        const int bn = nt * NT;
        float acc[2][8];
        #pragma unroll
        for (int i = 0; i < 2; i++)
            #pragma unroll
            for (int j = 0; j < 8; j++) acc[i][j] = 0.0f;

        for (int k0 = 0; k0 < Hn; k0 += KT) {
            float4 a4 = *reinterpret_cast<const float4*>(
                &h[(long long)(bm + arow)*Hn + k0 + akq]);
            As[arow][akq + 0] = a4.x; As[arow][akq + 1] = a4.y;
            As[arow][akq + 2] = a4.z; As[arow][akq + 3] = a4.w;
            *reinterpret_cast<float4*>(&Ws[wkk][wnq]) =
                *reinterpret_cast<const float4*>(
                    &Wq[(long long)(k0 + wkk)*Hn + bn + wnq]);
            __syncthreads();

            #pragma unroll
            for (int k = 0; k < KT; k++) {
                float a0 = As[ty*2    ][k];
                float a1 = As[ty*2 + 1][k];
                float4 w0 = *reinterpret_cast<const float4*>(&Ws[k][tx*8]);
                float4 w1 = *reinterpret_cast<const float4*>(&Ws[k][tx*8 + 4]);
                float wv[8] = {w0.x, w0.y, w0.z, w0.w, w1.x, w1.y, w1.z, w1.w};
                #pragma unroll
                for (int j = 0; j < 8; j++) {
                    acc[0][j] = fmaf(a0, wv[j], acc[0][j]);
                    acc[1][j] = fmaf(a1, wv[j], acc[1][j]);
                }
            }
            __syncthreads();
        }

        #pragma unroll
        for (int i = 0; i < 2; i++) {
            int row = bm + ty*2 + i;
            float4 o0, o1;
            o0.x = acc[i][0] + bq[bn + tx*8 + 0];
            o0.y = acc[i][1] + bq[bn + tx*8 + 1];
            o0.z = acc[i][2] + bq[bn + tx*8 + 2];
            o0.w = acc[i][3] + bq[bn + tx*8 + 3];
            o1.x = acc[i][4] + bq[bn + tx*8 + 4];
            o1.y = acc[i][5] + bq[bn + tx*8 + 5];
            o1.z = acc[i][6] + bq[bn + tx*8 + 6];
            o1.w = acc[i][7] + bq[bn + tx*8 + 7];
            float* cp = &cur[(long long)row*Hn + bn + tx*8];
            *reinterpret_cast<float4*>(cp)     = o0;
            *reinterpret_cast<float4*>(cp + 4) = o1;
        }
        __syncthreads();
    }
}

// ---------------------------------------------------------------------------
// Parallel leaky scan + spike (R11 verbatim). 64 blocks x 512 thr.
// ---------------------------------------------------------------------------
#define CHUNKS 16
#define CLEN   32
#define LPB    32

__global__ void __launch_bounds__(512)
scan_kernel(const float* __restrict__ cur,
            const float* __restrict__ beta,
            float* __restrict__ spk,
            const int* __restrict__ fcur,
            int* __restrict__ fs) {
    __shared__ float S[CHUNKS][LPB];
    __shared__ float Carry[CHUNKS][LPB];
    __shared__ int sel[Tn];

    const int tid  = threadIdx.x;
    const int w    = tid >> 5;
    const int l    = tid & 31;
    const int lane = blockIdx.x * LPB + l;
    const int b    = lane >> 8;
    const int hc   = lane & (Hn - 1);

    sel[tid] = fcur[tid * Bn + b];
    int any = __syncthreads_or(sel[tid]);
    if (!any) return;

    const float bt = beta[hc];
    const float* base = cur + (long long)(w * CLEN) * BH + lane;

    float m = 0.0f;
    #pragma unroll
    for (int j = 0; j < CLEN; j++) {
        float c = sel[w * CLEN + j] ? base[j * BH] : 0.0f;
        m = fmaf(bt, m, c);
    }
    S[w][l] = m;
    __syncthreads();

    if (w == 0) {
        float b2  = bt * bt;
        float b4  = b2 * b2;
        float b8  = b4 * b4;
        float b16 = b8 * b8;
        float b32 = b16 * b16;
        float c = 0.0f;
        #pragma unroll
        for (int k = 0; k < CHUNKS; k++) {
            Carry[k][l] = c;
            c = fmaf(b32, c, S[k][l]);
        }
    }
    __syncthreads();

    m = Carry[w][l];
    #pragma unroll
    for (int j = 0; j < CLEN; j++) {
        int t = w * CLEN + j;
        float c = sel[t] ? base[j * BH] : 0.0f;
        m = fmaf(bt, m, c);
        float s = (m > 1.0f) ? 1.0f : 0.0f;
        spk[(long long)t * BH + lane] = s;
        if (s != 0.0f) atomicOr(&fs[t * Bn + b], 1);
    }
}

// ---------------------------------------------------------------------------
// FUSED fc2 + vocab: out[64, 256v] tile. Null gate computed directly from
// spk row flags (fs) + bfc: h = relu(mask(spk)@Wfc + bfc) is logically zero
// iff no spike rows AND bfc == 0 -> out rows = bout (broadcast, streaming).
// Dense fallback (correctness-only; never taken on these inputs): recompute
// the h tile slab-by-slab from spk inside this block, then accumulate vocab.
// ---------------------------------------------------------------------------
#define NTV 256

__global__ void __launch_bounds__(256)
vocab_fused_kernel(const float* __restrict__ spk,
                   const float* __restrict__ Wfc,
                   const float* __restrict__ bfc,
                   const float* __restrict__ Wout,
                   const float* __restrict__ bout,
                   float* __restrict__ C,
                   const int* __restrict__ fs) {
    __shared__ int sflag[MT];
    const int bm = blockIdx.y * MT;
    const int bn = blockIdx.x * NTV;
    const int tid = threadIdx.x;

    if (tid < MT) sflag[tid] = fs[bm + tid];
    int bfcAny = __syncthreads_or(bfc[tid] != 0.0f);
    int anyflag = __syncthreads_or(tid < MT ? sflag[tid] : 0);

    if (!anyflag && !bfcAny) {
        // h tile logically zero: out = bout broadcast
        int c4 = (tid & 63) * 4;
        int r0 = tid >> 6;
        float4 bv = *reinterpret_cast<const float4*>(&bout[bn + c4]);
        #pragma unroll
        for (int r = r0; r < MT; r += 4)
            __stwt(reinterpret_cast<float4*>(&C[(long long)(bm + r)*Vn + bn + c4]), bv);
        return;
    }

    // ---- dense fallback: recompute h tile from spk, slab by slab ----------
    __shared__ __align__(16) float Ss[MT][KT + 1];     // spk slab (masked)
    __shared__ __align__(16) float Wf[KT][KT + 4];     // Wfc sub-block
    __shared__ __align__(16) float Hs[MT][KT + 1];     // h sub-tile (relu'd)
    __shared__ __align__(16) float Wo[KT][NTV + 4];    // Wout slab

    const int ty = tid >> 4;       // 0..15 -> 4-row group
    const int tx = tid & 15;       // 0..15 -> 16-col group
    const int hrow = tid >> 2;     // 0..63
    const int hcq  = (tid & 3) * 4;

    float acc[4][16];
    #pragma unroll
    for (int i = 0; i < 4; i++)
        #pragma unroll
        for (int j = 0; j < 16; j++) acc[i][j] = 0.0f;

    for (int k0 = 0; k0 < Hn; k0 += KT) {
        // Hs[64][16] = relu( mask(spk)[64][:] @ Wfc[:, k0:k0+16] + bfc[k0:] )
        float hacc[4] = {0.0f, 0.0f, 0.0f, 0.0f};
        for (int kk0 = 0; kk0 < Hn; kk0 += KT) {
            float4 a4 = *reinterpret_cast<const float4*>(
                &spk[(long long)(bm + hrow)*Hn + kk0 + hcq]);
            if (!sflag[hrow]) { a4.x = a4.y = a4.z = a4.w = 0.0f; }
            Ss[hrow][hcq + 0] = a4.x; Ss[hrow][hcq + 1] = a4.y;
            Ss[hrow][hcq + 2] = a4.z; Ss[hrow][hcq + 3] = a4.w;
            {
                int r = tid >> 4, c = tid & 15;
                Wf[r][c] = Wfc[(long long)(kk0 + r)*Hn + k0 + c];
            }
            __syncthreads();
            #pragma unroll
            for (int kk = 0; kk < KT; kk++) {
                float s = Ss[hrow][kk];
                hacc[0] = fmaf(s, Wf[kk][hcq + 0], hacc[0]);
                hacc[1] = fmaf(s, Wf[kk][hcq + 1], hacc[1]);
                hacc[2] = fmaf(s, Wf[kk][hcq + 2], hacc[2]);
                hacc[3] = fmaf(s, Wf[kk][hcq + 3], hacc[3]);
            }
            __syncthreads();
        }
        Hs[hrow][hcq + 0] = fmaxf(hacc[0] + bfc[k0 + hcq + 0], 0.0f);
        Hs[hrow][hcq + 1] = fmaxf(hacc[1] + bfc[k0 + hcq + 1], 0.0f);
        Hs[hrow][hcq + 2] = fmaxf(hacc[2] + bfc[k0 + hcq + 2], 0.0f);
        Hs[hrow][hcq + 3] = fmaxf(hacc[3] + bfc[k0 + hcq + 3], 0.0f);

        // stage Wout slab 16x256
        #pragma unroll
        for (int it = 0; it < 4; it++) {
            int f = tid + it * 256;
            int kk = f >> 6;
            int nq = (f & 63) * 4;
            *reinterpret_cast<float4*>(&Wo[kk][nq]) =
                *reinterpret_cast<const float4*>(
                    &Wout[(long long)(k0 + kk)*Vn + bn + nq]);
        }
        __syncthreads();   // Hs + Wo visible

        #pragma unroll
        for (int k = 0; k < KT; k++) {
            float a0 = Hs[ty*4 + 0][k];
            float a1 = Hs[ty*4 + 1][k];
            float a2 = Hs[ty*4 + 2][k];
            float a3 = Hs[ty*4 + 3][k];
            #pragma unroll
            for (int jq = 0; jq < 4; jq++) {
                float4 wq = *reinterpret_cast<const float4*>(&Wo[k][tx*16 + jq*4]);
                float wv[4] = {wq.x, wq.y, wq.z, wq.w};
                #pragma unroll
                for (int j = 0; j < 4; j++) {
                    acc[0][jq*4 + j] = fmaf(a0, wv[j], acc[0][jq*4 + j]);
                    acc[1][jq*4 + j] = fmaf(a1, wv[j], acc[1][jq*4 + j]);
                    acc[2][jq*4 + j] = fmaf(a2, wv[j], acc[2][jq*4 + j]);
                    acc[3][jq*4 + j] = fmaf(a3, wv[j], acc[3][jq*4 + j]);
                }
            }
        }
        __syncthreads();   // protect Hs/Wo/Ss reuse next slab
    }

    #pragma unroll
    for (int i = 0; i < 4; i++) {
        int row = bm + ty*4 + i;
        #pragma unroll
        for (int jq = 0; jq < 4; jq++) {
            float4 o;
            o.x = acc[i][jq*4 + 0] + bout[bn + tx*16 + jq*4 + 0];
            o.y = acc[i][jq*4 + 1] + bout[bn + tx*16 + jq*4 + 1];
            o.z = acc[i][jq*4 + 2] + bout[bn + tx*16 + jq*4 + 2];
            o.w = acc[i][jq*4 + 3] + bout[bn + tx*16 + jq*4 + 3];
            *reinterpret_cast<float4*>(&C[(long long)row*Vn + bn + tx*16 + jq*4]) = o;
        }
    }
}

// ---------------------------------------------------------------------------
// launch: embed+q0, scan0, [fc0+q1], scan1, [fc1+q2], scan2, [fc2+vocab]
// ---------------------------------------------------------------------------
extern "C" void kernel_launch(void* const* d_in, const int* in_sizes, int n_in,
                              void* d_out, int out_size) {
    const int*   tokens  = (const int*)  d_in[0];
    const float* tok_emb = (const float*)d_in[1];
    const float* pos_emb = (const float*)d_in[2];
    const float* Wq      = (const float*)d_in[3];
    const float* bq      = (const float*)d_in[4];
    const float* beta    = (const float*)d_in[5];
    const float* Wfc     = (const float*)d_in[6];
    const float* bfc     = (const float*)d_in[7];
    const float* Wout    = (const float*)d_in[8];
    const float* bout    = (const float*)d_in[9];
    float* out = (float*)d_out;

    float *cur, *spk, *h;
    int *fcur, *fs;
    cudaGetSymbolAddress((void**)&cur,  g_cur);
    cudaGetSymbolAddress((void**)&spk,  g_spk);
    cudaGetSymbolAddress((void**)&h,    g_h);
    cudaGetSymbolAddress((void**)&fcur, g_fcur);
    cudaGetSymbolAddress((void**)&fs,   g_fs);

    dim3 gsmall(Hn / NT, Mn / MT);   // (4, 64)

    // layer 0 q-projection (fused embedding, tf32)
    gemm_embed_kernel<<<gsmall, 256>>>(tokens, tok_emb, pos_emb,
                                       Wq, bq, cur, fcur, fs);
    scan_kernel<<<BH / LPB, 512>>>(cur, beta, spk, fcur, fs);

    // fused [fc_l + q_{l+1}] for l = 0, 1
    for (int l = 0; l < Ln - 1; l++) {
        fused_fc_q_kernel<<<Mn / MT, 256>>>(
            spk, Wfc + (long long)l*Hn*Hn, bfc + l*Hn,
            Wq + (long long)(l+1)*Hn*Hn, bq + (l+1)*Hn,
            h, cur, fs, fcur);
        scan_kernel<<<BH / LPB, 512>>>(cur, beta + (l+1)*Hn, spk, fcur, fs);
    }

    // fused fc2 + vocab (null gate from fs + bfc; dense fallback recomputes h)
    dim3 gbig(Vn / NTV, Mn / MT);    // (125, 64)
    vocab_fused_kernel<<<gbig, 256>>>(spk, Wfc + (long long)2*Hn*Hn,
                                      bfc + 2*Hn, Wout, bout, out, fs);
}

// round 15
// speedup vs baseline: 1.0323x; 1.0048x over previous
#include <cuda_runtime.h>

// Problem constants
#define Tn 512
#define Bn 8
#define Hn 256
#define Vn 32000
#define Ln 3
#define Mn (Tn*Bn)   // 4096
#define BH (Bn*Hn)   // 2048

// Scratch (device globals; allocation forbidden in kernel_launch)
__device__ float g_cur[Mn*Hn];
__device__ float g_spk[Mn*Hn];
__device__ float g_h  [Mn*Hn];
__device__ int   g_fcur[Mn];
__device__ int   g_fs  [Mn];

#define MT 64
#define NT 64
#define KT 16
#define SLAB 32     // k-slab for gemm_embed
#define ASTRIDE (SLAB + 4)   // 36
#define WSTRIDE (NT + 8)     // 72
#define NBUF 3
// dynamic smem: As[3][64][36] + Ws[3][32][72] + stok[64]
#define SMEM_AS_FLOATS (NBUF * MT * ASTRIDE)
#define SMEM_WS_FLOATS (NBUF * SLAB * WSTRIDE)
#define SMEM_EMBED_BYTES ((SMEM_AS_FLOATS + SMEM_WS_FLOATS) * 4 + MT * 4)

// ---------------------------------------------------------------------------
// tf32 mma.sync (m16n8k8, row.col, fp32 accum). Raw fp32 bits as tf32 (RZ).
// Precision: spike threshold sits ~11 sigma above |mem| on these scales, so
// tf32 rounding of cur cannot flip any spike (empirically rel_err=0).
// ---------------------------------------------------------------------------
__device__ __forceinline__ void mma_tf32(float* d, const unsigned* a,
                                         const unsigned* b) {
    asm volatile(
        "mma.sync.aligned.m16n8k8.row.col.f32.tf32.tf32.f32 "
        "{%0,%1,%2,%3}, {%4,%5,%6,%7}, {%8,%9}, {%0,%1,%2,%3};"
        : "+f"(d[0]), "+f"(d[1]), "+f"(d[2]), "+f"(d[3])
        : "r"(a[0]), "r"(a[1]), "r"(a[2]), "r"(a[3]),
          "r"(b[0]), "r"(b[1]));
}

// ---------------------------------------------------------------------------
// Layer-0 q-GEMM with fused embedding — tf32, TRIPLE-buffered (prefetch
// distance 2: loads for slab s+2 issue while slab s computes, hiding full
// DRAM latency on the tok_emb gathers). Tile 64x64, 256 thr = 8 warps.
// Also: fcur=1, fs=0.
// ---------------------------------------------------------------------------
__global__ void __launch_bounds__(256)
gemm_embed_kernel(const int* __restrict__ tokens,
                  const float* __restrict__ tok_emb,
                  const float* __restrict__ pos_emb,
                  const float* __restrict__ W,
                  const float* __restrict__ bias,
                  float* __restrict__ C,
                  int* __restrict__ fcur,
                  int* __restrict__ fs_zero) {
    extern __shared__ float sdyn[];
    float* AsBase = sdyn;                       // [NBUF][MT][ASTRIDE]
    float* WsBase = sdyn + SMEM_AS_FLOATS;      // [NBUF][SLAB][WSTRIDE]
    int*   stok   = (int*)(sdyn + SMEM_AS_FLOATS + SMEM_WS_FLOATS);

    const int bm = blockIdx.y * MT;
    const int bn = blockIdx.x * NT;
    const int tid = threadIdx.x;
    const int wid = tid >> 5;
    const int lane = tid & 31;

    if (tid < MT) stok[tid] = tokens[bm + tid];
    if (blockIdx.x == 0 && tid < MT) {
        fcur[bm + tid] = 1;
        fs_zero[bm + tid] = 0;
    }
    __syncthreads();

    // staging indices: A = 64 rows x 32 k (512 float4, 2/thread);
    // W = 32 k x 64 n (512 float4, 2/thread)
    const int af0 = tid,        ar0s = af0 >> 3, ak0s = (af0 & 7) * 4;
    const int af1 = tid + 256,  ar1s = af1 >> 3, ak1s = (af1 & 7) * 4;
    const int wf0 = tid,        wk0s = wf0 >> 4, wn0s = (wf0 & 15) * 4;
    const int wf1 = tid + 256,  wk1s = wf1 >> 4, wn1s = (wf1 & 15) * 4;
    const long long atok0 = (long long)stok[ar0s] * Hn;
    const long long atok1 = (long long)stok[ar1s] * Hn;
    const int apos0 = ((bm + ar0s) >> 3) * Hn;
    const int apos1 = ((bm + ar1s) >> 3) * Hn;

    // load helpers (macro-free lambdas)
    auto loadSlab = [&](int k0, float4& a0, float4& a1, float4& w0, float4& w1) {
        float4 e0 = *reinterpret_cast<const float4*>(&tok_emb[atok0 + k0 + ak0s]);
        float4 p0 = *reinterpret_cast<const float4*>(&pos_emb[apos0 + k0 + ak0s]);
        a0 = make_float4(e0.x+p0.x, e0.y+p0.y, e0.z+p0.z, e0.w+p0.w);
        float4 e1 = *reinterpret_cast<const float4*>(&tok_emb[atok1 + k0 + ak1s]);
        float4 p1 = *reinterpret_cast<const float4*>(&pos_emb[apos1 + k0 + ak1s]);
        a1 = make_float4(e1.x+p1.x, e1.y+p1.y, e1.z+p1.z, e1.w+p1.w);
        w0 = *reinterpret_cast<const float4*>(&W[(long long)(k0 + wk0s)*Hn + bn + wn0s]);
        w1 = *reinterpret_cast<const float4*>(&W[(long long)(k0 + wk1s)*Hn + bn + wn1s]);
    };
    auto storeSlab = [&](int buf, float4 a0, float4 a1, float4 w0, float4 w1) {
        float* A = AsBase + buf * (MT * ASTRIDE);
        float* Wp = WsBase + buf * (SLAB * WSTRIDE);
        *reinterpret_cast<float4*>(&A[ar0s * ASTRIDE + ak0s]) = a0;
        *reinterpret_cast<float4*>(&A[ar1s * ASTRIDE + ak1s]) = a1;
        *reinterpret_cast<float4*>(&Wp[wk0s * WSTRIDE + wn0s]) = w0;
        *reinterpret_cast<float4*>(&Wp[wk1s * WSTRIDE + wn1s]) = w1;
    };

    // prologue: slab 0 staged; slab 1 held in pending regs
    float4 pA0, pA1, pW0, pW1;      // pending (slab s+1)
    float4 nA0, nA1, nW0, nW1;      // in-flight (slab s+2)
    {
        float4 a0, a1, w0, w1;
        loadSlab(0, a0, a1, w0, w1);
        storeSlab(0, a0, a1, w0, w1);
        loadSlab(SLAB, pA0, pA1, pW0, pW1);
    }
    __syncthreads();

    float d[4][4];
    #pragma unroll
    for (int nf = 0; nf < 4; nf++)
        #pragma unroll
        for (int i = 0; i < 4; i++) d[nf][i] = 0.0f;

    const int strip = (wid >> 1) * 16;
    const int nh    = (wid & 1) * 32;
    const int ar0 = strip + (lane >> 2);
    const int ac0 = lane & 3;
    const int bk0 = lane & 3;
    const int bn0 = lane >> 2;

    const int NSLAB = Hn / SLAB;   // 8
    for (int s = 0; s < NSLAB; s++) {
        // issue loads for slab s+2 (distance-2 prefetch)
        if (s + 2 < NSLAB) {
            loadSlab((s + 2) * SLAB, nA0, nA1, nW0, nW1);
        }

        // compute on buffer s%3
        const float* A = AsBase + (s % NBUF) * (MT * ASTRIDE);
        const float* Wp = WsBase + (s % NBUF) * (SLAB * WSTRIDE);
        #pragma unroll
        for (int kb = 0; kb < SLAB; kb += 8) {
            unsigned a[4];
            a[0] = __float_as_uint(A[(ar0    ) * ASTRIDE + kb + ac0    ]);
            a[1] = __float_as_uint(A[(ar0 + 8) * ASTRIDE + kb + ac0    ]);
            a[2] = __float_as_uint(A[(ar0    ) * ASTRIDE + kb + ac0 + 4]);
            a[3] = __float_as_uint(A[(ar0 + 8) * ASTRIDE + kb + ac0 + 4]);
            #pragma unroll
            for (int nf = 0; nf < 4; nf++) {
                unsigned b[2];
                b[0] = __float_as_uint(Wp[(kb + bk0    ) * WSTRIDE + nh + nf*8 + bn0]);
                b[1] = __float_as_uint(Wp[(kb + bk0 + 4) * WSTRIDE + nh + nf*8 + bn0]);
                mma_tf32(d[nf], a, b);
            }
        }

        // store pending slab s+1 into buffer (s+1)%3 (distinct from compute buf)
        if (s + 1 < NSLAB) {
            storeSlab((s + 1) % NBUF, pA0, pA1, pW0, pW1);
            pA0 = nA0; pA1 = nA1; pW0 = nW0; pW1 = nW1;
            __syncthreads();
        }
    }

    const int orow = strip + (lane >> 2);
    const int oc = (lane & 3) * 2;
    #pragma unroll
    for (int nf = 0; nf < 4; nf++) {
        int c = bn + nh + nf*8 + oc;
        float b0 = bias[c], b1 = bias[c + 1];
        float2 o0 = make_float2(d[nf][0] + b0, d[nf][1] + b1);
        float2 o1 = make_float2(d[nf][2] + b0, d[nf][3] + b1);
        *reinterpret_cast<float2*>(&C[(long long)(bm + orow)*Hn + c])     = o0;
        *reinterpret_cast<float2*>(&C[(long long)(bm + orow + 8)*Hn + c]) = o1;
    }
}

// ---------------------------------------------------------------------------
// FUSED fc_l + q_{l+1} (R11 winner, verbatim): one block owns a 64-row strip.
// ---------------------------------------------------------------------------
__global__ void __launch_bounds__(256)
fused_fc_q_kernel(const float* __restrict__ spk,
                  const float* __restrict__ Wfc,
                  const float* __restrict__ bfc,
                  const float* __restrict__ Wq,
                  const float* __restrict__ bq,
                  float* __restrict__ h,
                  float* __restrict__ cur,
                  int* __restrict__ fs,
                  int* __restrict__ fcur)
{
    __shared__ __align__(16) float As[MT][KT + 1];
    __shared__ __align__(16) float Ws[KT][NT + 4];
    __shared__ int sflag[MT];

    const int bm = blockIdx.x * MT;
    const int tid = threadIdx.x;

    if (tid < MT) sflag[tid] = fs[bm + tid];
    int bfcAny = __syncthreads_or(bfc[tid] != 0.0f);
    int bqAny  = __syncthreads_or(bq[tid]  != 0.0f);
    int anyflag = __syncthreads_or(tid < MT ? sflag[tid] : 0);
    if (tid < MT) fs[bm + tid] = 0;

    if (!anyflag && !bfcAny) {
        if (tid < MT) fcur[bm + tid] = bqAny;
        if (bqAny) {
            int c4 = (tid & 63) * 4;
            int r0 = tid >> 6;
            float4 bv = *reinterpret_cast<const float4*>(&bq[c4]);
            #pragma unroll
            for (int r = r0; r < MT; r += 4)
                *reinterpret_cast<float4*>(&cur[(long long)(bm + r)*Hn + c4]) = bv;
        }
        return;
    }

    if (tid < MT) fcur[bm + tid] = 1;

    const int ty = tid >> 3;
    const int tx = tid & 7;
    const int arow = tid >> 2, akq = (tid & 3) * 4;
    const int wkk = tid >> 4, wnq = (tid & 15) * 4;

    // phase 1: fc (masked spk) -> h strip
    for (int nt = 0; nt < 4; nt++) {
        const int bn = nt * NT;
        float acc[2][8];
        #pragma unroll
        for (int i = 0; i < 2; i++)
            #pragma unroll
            for (int j = 0; j < 8; j++) acc[i][j] = 0.0f;

        for (int k0 = 0; k0 < Hn; k0 += KT) {
            float4 a4 = *reinterpret_cast<const float4*>(
                &spk[(long long)(bm + arow)*Hn + k0 + akq]);
            if (!sflag[arow]) { a4.x = a4.y = a4.z = a4.w = 0.0f; }
            As[arow][akq + 0] = a4.x; As[arow][akq + 1] = a4.y;
            As[arow][akq + 2] = a4.z; As[arow][akq + 3] = a4.w;
            *reinterpret_cast<float4*>(&Ws[wkk][wnq]) =
                *reinterpret_cast<const float4*>(
                    &Wfc[(long long)(k0 + wkk)*Hn + bn + wnq]);
            __syncthreads();

            #pragma unroll
            for (int k = 0; k < KT; k++) {
                float a0 = As[ty*2    ][k];
                float a1 = As[ty*2 + 1][k];
                float4 w0 = *reinterpret_cast<const float4*>(&Ws[k][tx*8]);
                float4 w1 = *reinterpret_cast<const float4*>(&Ws[k][tx*8 + 4]);
                float wv[8] = {w0.x, w0.y, w0.z, w0.w, w1.x, w1.y, w1.z, w1.w};
                #pragma unroll
                for (int j = 0; j < 8; j++) {
                    acc[0][j] = fmaf(a0, wv[j], acc[0][j]);
                    acc[1][j] = fmaf(a1, wv[j], acc[1][j]);
                }
            }
            __syncthreads();
        }

        #pragma unroll
        for (int i = 0; i < 2; i++) {
            int row = bm + ty*2 + i;
            float4 o0, o1;
            o0.x = fmaxf(acc[i][0] + bfc[bn + tx*8 + 0], 0.0f);
            o0.y = fmaxf(acc[i][1] + bfc[bn + tx*8 + 1], 0.0f);
            o0.z = fmaxf(acc[i][2] + bfc[bn + tx*8 + 2], 0.0f);
            o0.w = fmaxf(acc[i][3] + bfc[bn + tx*8 + 3], 0.0f);
            o1.x = fmaxf(acc[i][4] + bfc[bn + tx*8 + 4], 0.0f);
            o1.y = fmaxf(acc[i][5] + bfc[bn + tx*8 + 5], 0.0f);
            o1.z = fmaxf(acc[i][6] + bfc[bn + tx*8 + 6], 0.0f);
            o1.w = fmaxf(acc[i][7] + bfc[bn + tx*8 + 7], 0.0f);
            float* hp = &h[(long long)row*Hn + bn + tx*8];
            *reinterpret_cast<float4*>(hp)     = o0;
            *reinterpret_cast<float4*>(hp + 4) = o1;
        }
        __syncthreads();
    }
    __syncthreads();

    // phase 2: q (dense h strip) -> cur strip
    for (int nt = 0; nt < 4; nt++) {
        const int bn = nt * NT;
        float acc[2][8];
        #pragma unroll
        for (int i = 0; i < 2; i++)
            #pragma unroll
            for (int j = 0; j < 8; j++) acc[i][j] = 0.0f;

        for (int k0 = 0; k0 < Hn; k0 += KT) {
            float4 a4 = *reinterpret_cast<const float4*>(
                &h[(long long)(bm + arow)*Hn + k0 + akq]);
            As[arow][akq + 0] = a4.x; As[arow][akq + 1] = a4.y;
            As[arow][akq + 2] = a4.z; As[arow][akq + 3] = a4.w;
            *reinterpret_cast<float4*>(&Ws[wkk][wnq]) =
                *reinterpret_cast<const float4*>(
                    &Wq[(long long)(k0 + wkk)*Hn + bn + wnq]);
            __syncthreads();

            #pragma unroll
            for (int k = 0; k < KT; k++) {
                float a0 = As[ty*2    ][k];
                float a1 = As[ty*2 + 1][k];
                float4 w0 = *reinterpret_cast<const float4*>(&Ws[k][tx*8]);
                float4 w1 = *reinterpret_cast<const float4*>(&Ws[k][tx*8 + 4]);
                float wv[8] = {w0.x, w0.y, w0.z, w0.w, w1.x, w1.y, w1.z, w1.w};
                #pragma unroll
                for (int j = 0; j < 8; j++) {
                    acc[0][j] = fmaf(a0, wv[j], acc[0][j]);
                    acc[1][j] = fmaf(a1, wv[j], acc[1][j]);
                }
            }
            __syncthreads();
        }

        #pragma unroll
        for (int i = 0; i < 2; i++) {
            int row = bm + ty*2 + i;
            float4 o0, o1;
            o0.x = acc[i][0] + bq[bn + tx*8 + 0];
            o0.y = acc[i][1] + bq[bn + tx*8 + 1];
            o0.z = acc[i][2] + bq[bn + tx*8 + 2];
            o0.w = acc[i][3] + bq[bn + tx*8 + 3];
            o1.x = acc[i][4] + bq[bn + tx*8 + 4];
            o1.y = acc[i][5] + bq[bn + tx*8 + 5];
            o1.z = acc[i][6] + bq[bn + tx*8 + 6];
            o1.w = acc[i][7] + bq[bn + tx*8 + 7];
            float* cp = &cur[(long long)row*Hn + bn + tx*8];
            *reinterpret_cast<float4*>(cp)     = o0;
            *reinterpret_cast<float4*>(cp + 4) = o1;
        }
        __syncthreads();
    }
}

// ---------------------------------------------------------------------------
// Parallel leaky scan + spike (R11 verbatim). 64 blocks x 512 thr.
// ---------------------------------------------------------------------------
#define CHUNKS 16
#define CLEN   32
#define LPB    32

__global__ void __launch_bounds__(512)
scan_kernel(const float* __restrict__ cur,
            const float* __restrict__ beta,
            float* __restrict__ spk,
            const int* __restrict__ fcur,
            int* __restrict__ fs) {
    __shared__ float S[CHUNKS][LPB];
    __shared__ float Carry[CHUNKS][LPB];
    __shared__ int sel[Tn];

    const int tid  = threadIdx.x;
    const int w    = tid >> 5;
    const int l    = tid & 31;
    const int lane = blockIdx.x * LPB + l;
    const int b    = lane >> 8;
    const int hc   = lane & (Hn - 1);

    sel[tid] = fcur[tid * Bn + b];
    int any = __syncthreads_or(sel[tid]);
    if (!any) return;

    const float bt = beta[hc];
    const float* base = cur + (long long)(w * CLEN) * BH + lane;

    float m = 0.0f;
    #pragma unroll
    for (int j = 0; j < CLEN; j++) {
        float c = sel[w * CLEN + j] ? base[j * BH] : 0.0f;
        m = fmaf(bt, m, c);
    }
    S[w][l] = m;
    __syncthreads();

    if (w == 0) {
        float b2  = bt * bt;
        float b4  = b2 * b2;
        float b8  = b4 * b4;
        float b16 = b8 * b8;
        float b32 = b16 * b16;
        float c = 0.0f;
        #pragma unroll
        for (int k = 0; k < CHUNKS; k++) {
            Carry[k][l] = c;
            c = fmaf(b32, c, S[k][l]);
        }
    }
    __syncthreads();

    m = Carry[w][l];
    #pragma unroll
    for (int j = 0; j < CLEN; j++) {
        int t = w * CLEN + j;
        float c = sel[t] ? base[j * BH] : 0.0f;
        m = fmaf(bt, m, c);
        float s = (m > 1.0f) ? 1.0f : 0.0f;
        spk[(long long)t * BH + lane] = s;
        if (s != 0.0f) atomicOr(&fs[t * Bn + b], 1);
    }
}

// ---------------------------------------------------------------------------
// FUSED fc2 + vocab (R14 winner, verbatim): null gate from fs + bfc.
// ---------------------------------------------------------------------------
#define NTV 256

__global__ void __launch_bounds__(256)
vocab_fused_kernel(const float* __restrict__ spk,
                   const float* __restrict__ Wfc,
                   const float* __restrict__ bfc,
                   const float* __restrict__ Wout,
                   const float* __restrict__ bout,
                   float* __restrict__ C,
                   const int* __restrict__ fs) {
    __shared__ int sflag[MT];
    const int bm = blockIdx.y * MT;
    const int bn = blockIdx.x * NTV;
    const int tid = threadIdx.x;

    if (tid < MT) sflag[tid] = fs[bm + tid];
    int bfcAny = __syncthreads_or(bfc[tid] != 0.0f);
    int anyflag = __syncthreads_or(tid < MT ? sflag[tid] : 0);

    if (!anyflag && !bfcAny) {
        int c4 = (tid & 63) * 4;
        int r0 = tid >> 6;
        float4 bv = *reinterpret_cast<const float4*>(&bout[bn + c4]);
        #pragma unroll
        for (int r = r0; r < MT; r += 4)
            __stwt(reinterpret_cast<float4*>(&C[(long long)(bm + r)*Vn + bn + c4]), bv);
        return;
    }

    // dense fallback: recompute h tile from spk, slab by slab
    __shared__ __align__(16) float Ss[MT][KT + 1];
    __shared__ __align__(16) float Wf[KT][KT + 4];
    __shared__ __align__(16) float Hs[MT][KT + 1];
    __shared__ __align__(16) float Wo[KT][NTV + 4];

    const int ty = tid >> 4;
    const int tx = tid & 15;
    const int hrow = tid >> 2;
    const int hcq  = (tid & 3) * 4;

    float acc[4][16];
    #pragma unroll
    for (int i = 0; i < 4; i++)
        #pragma unroll
        for (int j = 0; j < 16; j++) acc[i][j] = 0.0f;

    for (int k0 = 0; k0 < Hn; k0 += KT) {
        float hacc[4] = {0.0f, 0.0f, 0.0f, 0.0f};
        for (int kk0 = 0; kk0 < Hn; kk0 += KT) {
            float4 a4 = *reinterpret_cast<const float4*>(
                &spk[(long long)(bm + hrow)*Hn + kk0 + hcq]);
            if (!sflag[hrow]) { a4.x = a4.y = a4.z = a4.w = 0.0f; }
            Ss[hrow][hcq + 0] = a4.x; Ss[hrow][hcq + 1] = a4.y;
            Ss[hrow][hcq + 2] = a4.z; Ss[hrow][hcq + 3] = a4.w;
            {
                int r = tid >> 4, c = tid & 15;
                Wf[r][c] = Wfc[(long long)(kk0 + r)*Hn + k0 + c];
            }
            __syncthreads();
            #pragma unroll
            for (int kk = 0; kk < KT; kk++) {
                float s = Ss[hrow][kk];
                hacc[0] = fmaf(s, Wf[kk][hcq + 0], hacc[0]);
                hacc[1] = fmaf(s, Wf[kk][hcq + 1], hacc[1]);
                hacc[2] = fmaf(s, Wf[kk][hcq + 2], hacc[2]);
                hacc[3] = fmaf(s, Wf[kk][hcq + 3], hacc[3]);
            }
            __syncthreads();
        }
        Hs[hrow][hcq + 0] = fmaxf(hacc[0] + bfc[k0 + hcq + 0], 0.0f);
        Hs[hrow][hcq + 1] = fmaxf(hacc[1] + bfc[k0 + hcq + 1], 0.0f);
        Hs[hrow][hcq + 2] = fmaxf(hacc[2] + bfc[k0 + hcq + 2], 0.0f);
        Hs[hrow][hcq + 3] = fmaxf(hacc[3] + bfc[k0 + hcq + 3], 0.0f);

        #pragma unroll
        for (int it = 0; it < 4; it++) {
            int f = tid + it * 256;
            int kk = f >> 6;
            int nq = (f & 63) * 4;
            *reinterpret_cast<float4*>(&Wo[kk][nq]) =
                *reinterpret_cast<const float4*>(
                    &Wout[(long long)(k0 + kk)*Vn + bn + nq]);
        }
        __syncthreads();

        #pragma unroll
        for (int k = 0; k < KT; k++) {
            float a0 = Hs[ty*4 + 0][k];
            float a1 = Hs[ty*4 + 1][k];
            float a2 = Hs[ty*4 + 2][k];
            float a3 = Hs[ty*4 + 3][k];
            #pragma unroll
            for (int jq = 0; jq < 4; jq++) {
                float4 wq = *reinterpret_cast<const float4*>(&Wo[k][tx*16 + jq*4]);
                float wv[4] = {wq.x, wq.y, wq.z, wq.w};
                #pragma unroll
                for (int j = 0; j < 4; j++) {
                    acc[0][jq*4 + j] = fmaf(a0, wv[j], acc[0][jq*4 + j]);
                    acc[1][jq*4 + j] = fmaf(a1, wv[j], acc[1][jq*4 + j]);
                    acc[2][jq*4 + j] = fmaf(a2, wv[j], acc[2][jq*4 + j]);
                    acc[3][jq*4 + j] = fmaf(a3, wv[j], acc[3][jq*4 + j]);
                }
            }
        }
        __syncthreads();
    }

    #pragma unroll
    for (int i = 0; i < 4; i++) {
        int row = bm + ty*4 + i;
        #pragma unroll
        for (int jq = 0; jq < 4; jq++) {
            float4 o;
            o.x = acc[i][jq*4 + 0] + bout[bn + tx*16 + jq*4 + 0];
            o.y = acc[i][jq*4 + 1] + bout[bn + tx*16 + jq*4 + 1];
            o.z = acc[i][jq*4 + 2] + bout[bn + tx*16 + jq*4 + 2];
            o.w = acc[i][jq*4 + 3] + bout[bn + tx*16 + jq*4 + 3];
            *reinterpret_cast<float4*>(&C[(long long)row*Vn + bn + tx*16 + jq*4]) = o;
        }
    }
}

// ---------------------------------------------------------------------------
// launch: embed+q0, scan0, [fc0+q1], scan1, [fc1+q2], scan2, [fc2+vocab]
// ---------------------------------------------------------------------------
extern "C" void kernel_launch(void* const* d_in, const int* in_sizes, int n_in,
                              void* d_out, int out_size) {
    const int*   tokens  = (const int*)  d_in[0];
    const float* tok_emb = (const float*)d_in[1];
    const float* pos_emb = (const float*)d_in[2];
    const float* Wq      = (const float*)d_in[3];
    const float* bq      = (const float*)d_in[4];
    const float* beta    = (const float*)d_in[5];
    const float* Wfc     = (const float*)d_in[6];
    const float* bfc     = (const float*)d_in[7];
    const float* Wout    = (const float*)d_in[8];
    const float* bout    = (const float*)d_in[9];
    float* out = (float*)d_out;

    float *cur, *spk, *h;
    int *fcur, *fs;
    cudaGetSymbolAddress((void**)&cur,  g_cur);
    cudaGetSymbolAddress((void**)&spk,  g_spk);
    cudaGetSymbolAddress((void**)&h,    g_h);
    cudaGetSymbolAddress((void**)&fcur, g_fcur);
    cudaGetSymbolAddress((void**)&fs,   g_fs);

    cudaFuncSetAttribute(gemm_embed_kernel,
                         cudaFuncAttributeMaxDynamicSharedMemorySize,
                         SMEM_EMBED_BYTES);

    dim3 gsmall(Hn / NT, Mn / MT);   // (4, 64)

    // layer 0 q-projection (fused embedding, tf32, triple-buffered)
    gemm_embed_kernel<<<gsmall, 256, SMEM_EMBED_BYTES>>>(
        tokens, tok_emb, pos_emb, Wq, bq, cur, fcur, fs);
    scan_kernel<<<BH / LPB, 512>>>(cur, beta, spk, fcur, fs);

    // fused [fc_l + q_{l+1}] for l = 0, 1
    for (int l = 0; l < Ln - 1; l++) {
        fused_fc_q_kernel<<<Mn / MT, 256>>>(
            spk, Wfc + (long long)l*Hn*Hn, bfc + l*Hn,
            Wq + (long long)(l+1)*Hn*Hn, bq + (l+1)*Hn,
            h, cur, fs, fcur);
        scan_kernel<<<BH / LPB, 512>>>(cur, beta + (l+1)*Hn, spk, fcur, fs);
    }

    // fused fc2 + vocab (null gate from fs + bfc; dense fallback recomputes h)
    dim3 gbig(Vn / NTV, Mn / MT);    // (125, 64)
    vocab_fused_kernel<<<gbig, 256>>>(spk, Wfc + (long long)2*Hn*Hn,
                                      bfc + 2*Hn, Wout, bout, out, fs);
}